// round 13
// baseline (speedup 1.0000x reference)
#include <cuda_runtime.h>
#include <math.h>
#include <stdint.h>

// Problem constants
#define Bq 8
#define Tq 1024
#define Cq 1024
#define Hq 16
#define Dq 64
#define Mq (Bq * Tq)          // 8192 rows
#define BHq (Bq * Hq)         // 128

// ---------------------------------------------------------------------------
// Scratch (device globals; no dynamic allocation allowed)
// ---------------------------------------------------------------------------
__device__ float g_q[(size_t)BHq * Tq * Dq];      // [B,H,T,D]  32 MB
__device__ float g_k[(size_t)BHq * Tq * Dq];      // 32 MB
__device__ float g_v[(size_t)BHq * Tq * Dq];      // 32 MB
__device__ float g_ctx[(size_t)Mq * Cq];          // [B,T,C] fp32  32 MB
__device__ float g_wqkv[(size_t)3 * Cq * Cq];     // packed [3][N=HD][K=C] tf32
__device__ float g_wp[(size_t)Cq * Cq];           // Wproj tf32 [N,K]  4 MB
__device__ float g_invl[(size_t)BHq * Tq];        // 1/rowsum per (bh,t)

__device__ __forceinline__ float f2tf32(float a) {
    uint32_t r;
    asm("cvt.rna.tf32.f32 %0, %1;" : "=r"(r) : "f"(a));
    return __uint_as_float(r);
}
__device__ __forceinline__ uint32_t smem_u32(const void* p) {
    uint32_t a;
    asm("{ .reg .u64 t; cvta.to.shared.u64 t, %1; cvt.u32.u64 %0, t; }" : "=r"(a) : "l"(p));
    return a;
}

// ---------------------------------------------------------------------------
// Conversion / repack kernels
// ---------------------------------------------------------------------------
// Wq/Wk/Wv [H,C,D] -> packed [3][N=HD][K=C], tf32; blockIdx.y selects matrix
__global__ void conv_wqkv3_kernel(const float* __restrict__ Wq,
                                  const float* __restrict__ Wk,
                                  const float* __restrict__ Wv,
                                  float* __restrict__ P) {
    int i = blockIdx.x * blockDim.x + threadIdx.x;
    int z = blockIdx.y;
    const float* W = (z == 0) ? Wq : (z == 1) ? Wk : Wv;
    int n = i >> 10;
    int c = i & 1023;
    int h = n >> 6, d = n & 63;
    P[(size_t)z * Cq * Cq + (size_t)n * Cq + c] = f2tf32(W[((size_t)h * Cq + c) * Dq + d]);
}

// Wproj [N,K] -> tf32 [N,K] elementwise
__global__ void conv_wp_kernel(const float4* __restrict__ W, float4* __restrict__ P) {
    int i = blockIdx.x * blockDim.x + threadIdx.x;
    float4 v = W[i];
    v.x = f2tf32(v.x); v.y = f2tf32(v.y); v.z = f2tf32(v.z); v.w = f2tf32(v.w);
    P[i] = v;
}

// ---------------------------------------------------------------------------
// mma helper
// ---------------------------------------------------------------------------
__device__ __forceinline__ void mma_tf32(float c[4], uint32_t a0, uint32_t a1,
                                         uint32_t a2, uint32_t a3,
                                         uint32_t b0, uint32_t b1) {
    asm volatile(
        "mma.sync.aligned.m16n8k8.row.col.f32.tf32.tf32.f32 "
        "{%0,%1,%2,%3}, {%4,%5,%6,%7}, {%8,%9}, {%0,%1,%2,%3};"
        : "+f"(c[0]), "+f"(c[1]), "+f"(c[2]), "+f"(c[3])
        : "r"(a0), "r"(a1), "r"(a2), "r"(a3), "r"(b0), "r"(b1));
}

// ---------------------------------------------------------------------------
// Shared GEMM plumbing: CTA tile 128x128, K-chunk 32, 3-stage cp.async,
// 256 threads (8 warps 4x2, warp tile 32x64). A[M,K], B[N,K] row-major.
// ---------------------------------------------------------------------------
#define GST 36
#define STGF (2 * 128 * GST)               // floats per stage (A + B)
#define GEMM_SMEM_BYTES (3 * STGF * 4)     // 110592 B

#define GEMM_PRELUDE(Asrc, Bsrc, Ktot)                                          \
    const int tid  = threadIdx.x;                                               \
    const int wid  = tid >> 5;                                                  \
    const int lane = tid & 31;                                                  \
    const int row0 = blockIdx.y * 128;                                          \
    const int col0 = blockIdx.x * 128;                                          \
    const int wm   = (wid & 3) * 32;                                            \
    const int wn   = (wid >> 2) * 64;                                           \
    const uint32_t smb = smem_u32(smem);                                        \
    int lrow[4], lc4[4];                                                        \
    _Pragma("unroll")                                                           \
    for (int l = 0; l < 4; l++) {                                               \
        int idx = l * 256 + tid;                                                \
        lrow[l] = idx >> 3;                                                     \
        lc4[l]  = (idx & 7) << 2;                                               \
    }                                                                           \
    const int NC = (Ktot) >> 5;

#define ISSUE_STAGE(s, buf, Asrc, Bsrc, Ktot)                                   \
    do {                                                                        \
        const int k0 = (s) << 5;                                                \
        const uint32_t sb = smb + (uint32_t)(buf) * (STGF * 4);                 \
        _Pragma("unroll")                                                       \
        for (int l = 0; l < 4; l++) {                                           \
            uint32_t da = sb + (uint32_t)(lrow[l] * GST + lc4[l]) * 4;          \
            const float* sa = (Asrc) + (size_t)(row0 + lrow[l]) * (Ktot) + k0 + lc4[l]; \
            asm volatile("cp.async.cg.shared.global [%0], [%1], 16;"            \
                         :: "r"(da), "l"(sa));                                  \
            uint32_t db = sb + (uint32_t)(128 * GST + lrow[l] * GST + lc4[l]) * 4; \
            const float* sbp = (Bsrc) + (size_t)(col0 + lrow[l]) * (Ktot) + k0 + lc4[l]; \
            asm volatile("cp.async.cg.shared.global [%0], [%1], 16;"            \
                         :: "r"(db), "l"(sbp));                                 \
        }                                                                       \
        asm volatile("cp.async.commit_group;");                                 \
    } while (0)

#define LOAD_B_FRAGS(Bs_, kb)                                                   \
    uint32_t bf[8][2];                                                          \
    {                                                                           \
        const int brow = wn + (lane >> 2);                                      \
        const int bcol = (kb) + (lane & 3);                                     \
        _Pragma("unroll")                                                       \
        for (int nt = 0; nt < 8; nt++) {                                        \
            bf[nt][0] = __float_as_uint(Bs_[(brow + nt * 8) * GST + bcol    ]); \
            bf[nt][1] = __float_as_uint(Bs_[(brow + nt * 8) * GST + bcol + 4]); \
        }                                                                       \
    }

// ---------------------------------------------------------------------------
// QKV GEMM: A = raw x (tf32-rounded at fragment read), B = pre-rounded W.
// grid (8, 64, 3); scatter epilogue into [B,H,T,D].
// ---------------------------------------------------------------------------
__global__ __launch_bounds__(256) void gemm_qkv(
    const float* __restrict__ A, const float* __restrict__ BwBase,
    float* __restrict__ O0, float* __restrict__ O1, float* __restrict__ O2)
{
    extern __shared__ float smem[];
    const float* Bw = BwBase + (size_t)blockIdx.z * Cq * Cq;
    float* Cout = (blockIdx.z == 0) ? O0 : (blockIdx.z == 1) ? O1 : O2;

    GEMM_PRELUDE(A, Bw, Cq)

    float acc[2][8][4];
#pragma unroll
    for (int mt = 0; mt < 2; mt++)
#pragma unroll
        for (int nt = 0; nt < 8; nt++)
#pragma unroll
            for (int j = 0; j < 4; j++) acc[mt][nt][j] = 0.f;

    ISSUE_STAGE(0, 0, A, Bw, Cq);
    ISSUE_STAGE(1, 1, A, Bw, Cq);
    ISSUE_STAGE(2, 2, A, Bw, Cq);

    int cur = 0;
    for (int i = 0; i < NC; i++) {
        asm volatile("cp.async.wait_group 2;");
        __syncthreads();

        const float* As_ = smem + cur * STGF;
        const float* Bs_ = As_ + 128 * GST;

#pragma unroll
        for (int ks = 0; ks < 4; ks++) {
            const int kb = ks * 8;
            const int arow = wm + (lane >> 2);
            const int acol = kb + (lane & 3);
            uint32_t af[2][4];
#pragma unroll
            for (int mt = 0; mt < 2; mt++) {
                af[mt][0] = __float_as_uint(f2tf32(As_[(arow + mt * 16    ) * GST + acol    ]));
                af[mt][1] = __float_as_uint(f2tf32(As_[(arow + mt * 16 + 8) * GST + acol    ]));
                af[mt][2] = __float_as_uint(f2tf32(As_[(arow + mt * 16    ) * GST + acol + 4]));
                af[mt][3] = __float_as_uint(f2tf32(As_[(arow + mt * 16 + 8) * GST + acol + 4]));
            }
            LOAD_B_FRAGS(Bs_, kb)
#pragma unroll
            for (int mt = 0; mt < 2; mt++)
#pragma unroll
                for (int nt = 0; nt < 8; nt++)
                    mma_tf32(acc[mt][nt], af[mt][0], af[mt][1], af[mt][2], af[mt][3],
                             bf[nt][0], bf[nt][1]);
        }
        __syncthreads();

        if (i + 3 < NC) ISSUE_STAGE(i + 3, cur, A, Bw, Cq);
        else asm volatile("cp.async.commit_group;");
        cur = (cur == 2) ? 0 : cur + 1;
    }

    const int er = lane >> 2;
    const int ec = (lane & 3) << 1;
#pragma unroll
    for (int mt = 0; mt < 2; mt++) {
#pragma unroll
        for (int nt = 0; nt < 8; nt++) {
#pragma unroll
            for (int half = 0; half < 2; half++) {
                int m = row0 + wm + mt * 16 + er + half * 8;
                int b = m >> 10, t = m & 1023;
                int n = col0 + wn + nt * 8 + ec;
                int h = n >> 6, d = n & 63;
                float2 v = make_float2(acc[mt][nt][half * 2], acc[mt][nt][half * 2 + 1]);
                *(float2*)(Cout + ((size_t)(b * Hq + h) << 16) + ((size_t)t << 6) + d) = v;
            }
        }
    }
}

// ---------------------------------------------------------------------------
// Proj GEMM: A = raw fp32 ctx; in-register 2-term tf32 split (hi+lo), B = tf32
// Wproj. out[m,n] = sum ctx[m,k] W[n,k] + bias[n]. grid (8, 64).
// ---------------------------------------------------------------------------
__global__ __launch_bounds__(256) void gemm_proj(
    const float* __restrict__ A, const float* __restrict__ Bw,
    float* __restrict__ Cout, const float* __restrict__ bias)
{
    extern __shared__ float smem[];

    GEMM_PRELUDE(A, Bw, Cq)

    float acc[2][8][4];
#pragma unroll
    for (int mt = 0; mt < 2; mt++)
#pragma unroll
        for (int nt = 0; nt < 8; nt++)
#pragma unroll
            for (int j = 0; j < 4; j++) acc[mt][nt][j] = 0.f;

    ISSUE_STAGE(0, 0, A, Bw, Cq);
    ISSUE_STAGE(1, 1, A, Bw, Cq);
    ISSUE_STAGE(2, 2, A, Bw, Cq);

    int cur = 0;
    for (int i = 0; i < NC; i++) {
        asm volatile("cp.async.wait_group 2;");
        __syncthreads();

        const float* As_ = smem + cur * STGF;
        const float* Bs_ = As_ + 128 * GST;

#pragma unroll
        for (int ks = 0; ks < 4; ks++) {
            const int kb = ks * 8;
            const int arow = wm + (lane >> 2);
            const int acol = kb + (lane & 3);
            uint32_t ah[2][4], al[2][4];
#pragma unroll
            for (int mt = 0; mt < 2; mt++) {
                float r0 = As_[(arow + mt * 16    ) * GST + acol    ];
                float r1 = As_[(arow + mt * 16 + 8) * GST + acol    ];
                float r2 = As_[(arow + mt * 16    ) * GST + acol + 4];
                float r3 = As_[(arow + mt * 16 + 8) * GST + acol + 4];
                float h0 = f2tf32(r0), h1 = f2tf32(r1), h2 = f2tf32(r2), h3 = f2tf32(r3);
                ah[mt][0] = __float_as_uint(h0); al[mt][0] = __float_as_uint(f2tf32(r0 - h0));
                ah[mt][1] = __float_as_uint(h1); al[mt][1] = __float_as_uint(f2tf32(r1 - h1));
                ah[mt][2] = __float_as_uint(h2); al[mt][2] = __float_as_uint(f2tf32(r2 - h2));
                ah[mt][3] = __float_as_uint(h3); al[mt][3] = __float_as_uint(f2tf32(r3 - h3));
            }
            LOAD_B_FRAGS(Bs_, kb)
#pragma unroll
            for (int mt = 0; mt < 2; mt++)
#pragma unroll
                for (int nt = 0; nt < 8; nt++) {
                    mma_tf32(acc[mt][nt], ah[mt][0], ah[mt][1], ah[mt][2], ah[mt][3],
                             bf[nt][0], bf[nt][1]);
                    mma_tf32(acc[mt][nt], al[mt][0], al[mt][1], al[mt][2], al[mt][3],
                             bf[nt][0], bf[nt][1]);
                }
        }
        __syncthreads();

        if (i + 3 < NC) ISSUE_STAGE(i + 3, cur, A, Bw, Cq);
        else asm volatile("cp.async.commit_group;");
        cur = (cur == 2) ? 0 : cur + 1;
    }

    const int er = lane >> 2;
    const int ec = (lane & 3) << 1;
#pragma unroll
    for (int mt = 0; mt < 2; mt++) {
#pragma unroll
        for (int nt = 0; nt < 8; nt++) {
#pragma unroll
            for (int half = 0; half < 2; half++) {
                int m = row0 + wm + mt * 16 + er + half * 8;
                int n = col0 + wn + nt * 8 + ec;
                float2 v = make_float2(acc[mt][nt][half * 2] + bias[n],
                                       acc[mt][nt][half * 2 + 1] + bias[n + 1]);
                *(float2*)(Cout + (size_t)m * Cq + n) = v;
            }
        }
    }
}

// ---------------------------------------------------------------------------
// Fused attention, one pass, no-max softmax (scores bounded; diagonal => l>=1).
// Writes UNNORMALIZED E=exp(S) to wei, causal 64-granular tiles ONLY:
// warps 0-3 (rows 0-63) skip tile sT=2tB+1 entirely (fully masked for them).
// rescale_wei normalizes + zero-fills the rest. ctx=(E·V)/l fp32 to g_ctx.
// ---------------------------------------------------------------------------
#define AST 72
#define ATTN_SMEM_FLOATS (128 * AST + 64 * AST + 64 * AST + 128 * AST)

__global__ __launch_bounds__(256, 1) void attn_fused(float* __restrict__ wei) {
    extern __shared__ float sm[];
    float* Qs = sm;
    float* Ks = Qs + 128 * AST;
    float* Vs = Ks + 64 * AST;
    float* Ps = Vs + 64 * AST;

    const int tid  = threadIdx.x;
    const int wid  = tid >> 5;
    const int lane = tid & 31;
    const int tB   = blockIdx.x;
    const int bh   = blockIdx.y;
    const int wm   = wid * 16;
    const int trow0 = tB * 128 + wm + (lane >> 2);
    const int trow1 = trow0 + 8;

    const float* qb = g_q + (size_t)bh * Tq * Dq + (size_t)tB * 128 * Dq;
    const float* kb = g_k + (size_t)bh * Tq * Dq;
    const float* vb = g_v + (size_t)bh * Tq * Dq;
    float* wb = wei + (size_t)bh * Tq * Tq + (size_t)tB * 128 * Tq;

    const int lr = tid >> 4;
    const int lc = (tid & 15) << 2;

    // load Q tile (tf32-rounded, once)
#pragma unroll
    for (int l = 0; l < 8; l++) {
        int f = tid + l * 256;
        int r = f >> 4, c4 = (f & 15) << 2;
        float4 v = *(const float4*)(qb + (size_t)r * Dq + c4);
        Qs[r * AST + c4 + 0] = f2tf32(v.x);
        Qs[r * AST + c4 + 1] = f2tf32(v.y);
        Qs[r * AST + c4 + 2] = f2tf32(v.z);
        Qs[r * AST + c4 + 3] = f2tf32(v.w);
    }
    __syncthreads();

    // persistent Q fragments
    uint32_t af[8][4];
    {
        const int arow = wm + (lane >> 2);
#pragma unroll
        for (int ks = 0; ks < 8; ks++) {
            const int acol = ks * 8 + (lane & 3);
            af[ks][0] = __float_as_uint(Qs[(arow    ) * AST + acol    ]);
            af[ks][1] = __float_as_uint(Qs[(arow + 8) * AST + acol    ]);
            af[ks][2] = __float_as_uint(Qs[(arow    ) * AST + acol + 4]);
            af[ks][3] = __float_as_uint(Qs[(arow + 8) * AST + acol + 4]);
        }
    }

    const int nS = 2 * tB + 2;
    float l0 = 0.f, l1 = 0.f;
    float ctx[8][4];
#pragma unroll
    for (int nt = 0; nt < 8; nt++)
        { ctx[nt][0]=0.f; ctx[nt][1]=0.f; ctx[nt][2]=0.f; ctx[nt][3]=0.f; }

    float4 pk[4], pv[4];
#pragma unroll
    for (int l = 0; l < 4; l++) {
        int r = lr + l * 16;
        pk[l] = *(const float4*)(kb + (size_t)r * Dq + lc);
        pv[l] = *(const float4*)(vb + (size_t)r * Dq + lc);
    }

    for (int sT = 0; sT < nS; sT++) {
#pragma unroll
        for (int l = 0; l < 4; l++) {
            int r = lr + l * 16;
            Ks[r * AST + lc + 0] = f2tf32(pk[l].x);
            Ks[r * AST + lc + 1] = f2tf32(pk[l].y);
            Ks[r * AST + lc + 2] = f2tf32(pk[l].z);
            Ks[r * AST + lc + 3] = f2tf32(pk[l].w);
            Vs[r * AST + lc + 0] = f2tf32(pv[l].x);
            Vs[r * AST + lc + 1] = f2tf32(pv[l].y);
            Vs[r * AST + lc + 2] = f2tf32(pv[l].z);
            Vs[r * AST + lc + 3] = f2tf32(pv[l].w);
        }
        __syncthreads();

        if (sT + 1 < nS) {
            const size_t base = (size_t)((sT + 1) * 64) * Dq;
#pragma unroll
            for (int l = 0; l < 4; l++) {
                int r = lr + l * 16;
                pk[l] = *(const float4*)(kb + base + (size_t)r * Dq + lc);
                pv[l] = *(const float4*)(vb + base + (size_t)r * Dq + lc);
            }
        }

        // warps 0-3 (rows 0-63): tile sT == 2tB+1 is fully masked -> skip all
        const bool active = (sT <= 2 * tB) || (wm >= 64);
        if (active) {
            float sacc[8][4];
#pragma unroll
            for (int nt = 0; nt < 8; nt++)
                { sacc[nt][0]=0.f; sacc[nt][1]=0.f; sacc[nt][2]=0.f; sacc[nt][3]=0.f; }
#pragma unroll
            for (int ks = 0; ks < 8; ks++) {
                uint32_t bf[8][2];
#pragma unroll
                for (int nt = 0; nt < 8; nt++) {
                    int srow = nt * 8 + (lane >> 2);
                    int scol = ks * 8 + (lane & 3);
                    bf[nt][0] = __float_as_uint(Ks[srow * AST + scol]);
                    bf[nt][1] = __float_as_uint(Ks[srow * AST + scol + 4]);
                }
#pragma unroll
                for (int nt = 0; nt < 8; nt++)
                    mma_tf32(sacc[nt], af[ks][0], af[ks][1], af[ks][2], af[ks][3],
                             bf[nt][0], bf[nt][1]);
            }

            const bool mask = (sT >= 2 * tB);
            {
                const int pr = wm + (lane >> 2);
                const int pc = (lane & 3) << 1;
#pragma unroll
                for (int nt = 0; nt < 8; nt++) {
                    float s0v = sacc[nt][0] * 0.125f;
                    float s1v = sacc[nt][1] * 0.125f;
                    float s2v = sacc[nt][2] * 0.125f;
                    float s3v = sacc[nt][3] * 0.125f;
                    if (mask) {
                        int s0 = sT * 64 + nt * 8 + ((lane & 3) << 1);
                        if (s0     > trow0) s0v = -INFINITY;
                        if (s0 + 1 > trow0) s1v = -INFINITY;
                        if (s0     > trow1) s2v = -INFINITY;
                        if (s0 + 1 > trow1) s3v = -INFINITY;
                    }
                    float e0 = __expf(s0v), e1 = __expf(s1v);
                    float e2 = __expf(s2v), e3 = __expf(s3v);
                    l0 += e0 + e1;
                    l1 += e2 + e3;
                    Ps[(pr    ) * AST + nt * 8 + pc    ] = e0;
                    Ps[(pr    ) * AST + nt * 8 + pc + 1] = e1;
                    Ps[(pr + 8) * AST + nt * 8 + pc    ] = e2;
                    Ps[(pr + 8) * AST + nt * 8 + pc + 1] = e3;
                }
            }
        }
        __syncthreads();

        if (active) {
            // write unnormalized E for this warp's 16 rows:
            // 16 rows x 16 float4 = 256 float4, covered by lane + k*32, k=0..7
#pragma unroll
            for (int k = 0; k < 8; k++) {
                int idx = lane + k * 32;
                int rr = wm + (idx >> 4);
                int cc = (idx & 15) << 2;
                *(float4*)(wb + (size_t)rr * Tq + sT * 64 + cc) =
                    *(const float4*)(Ps + rr * AST + cc);
            }

            // ctx += E·V (P rna-rounded; V pre-rounded in smem)
#pragma unroll
            for (int ks = 0; ks < 8; ks++) {
                const int arow = wm + (lane >> 2);
                const int acol = ks * 8 + (lane & 3);
                uint32_t ap[4];
                ap[0] = __float_as_uint(f2tf32(Ps[(arow    ) * AST + acol    ]));
                ap[1] = __float_as_uint(f2tf32(Ps[(arow + 8) * AST + acol    ]));
                ap[2] = __float_as_uint(f2tf32(Ps[(arow    ) * AST + acol + 4]));
                ap[3] = __float_as_uint(f2tf32(Ps[(arow + 8) * AST + acol + 4]));
                uint32_t bv[8][2];
#pragma unroll
                for (int nt = 0; nt < 8; nt++) {
                    int vrow = ks * 8 + (lane & 3);
                    int vcol = nt * 8 + (lane >> 2);
                    bv[nt][0] = __float_as_uint(Vs[(vrow    ) * AST + vcol]);
                    bv[nt][1] = __float_as_uint(Vs[(vrow + 4) * AST + vcol]);
                }
#pragma unroll
                for (int nt = 0; nt < 8; nt++)
                    mma_tf32(ctx[nt], ap[0], ap[1], ap[2], ap[3], bv[nt][0], bv[nt][1]);
            }
        }
        __syncthreads();
    }

    l0 += __shfl_xor_sync(0xffffffffu, l0, 1);
    l0 += __shfl_xor_sync(0xffffffffu, l0, 2);
    l1 += __shfl_xor_sync(0xffffffffu, l1, 1);
    l1 += __shfl_xor_sync(0xffffffffu, l1, 2);
    const float inv0 = 1.0f / l0;
    const float inv1 = 1.0f / l1;

    if ((lane & 3) == 0) {
        g_invl[(size_t)bh * Tq + trow0] = inv0;
        g_invl[(size_t)bh * Tq + trow1] = inv1;
    }

    // write normalized ctx fp32 -> g_ctx [B,T,C]
    {
        const int b = bh >> 4, h = bh & 15;
        const int ec = (lane & 3) << 1;
#pragma unroll
        for (int nt = 0; nt < 8; nt++) {
            float2 v0 = {ctx[nt][0] * inv0, ctx[nt][1] * inv0};
            float2 v1 = {ctx[nt][2] * inv1, ctx[nt][3] * inv1};
            int c = h * 64 + nt * 8 + ec;
            *(float2*)(g_ctx + ((size_t)(b * Tq + trow0) << 10) + c) = v0;
            *(float2*)(g_ctx + ((size_t)(b * Tq + trow1) << 10) + c) = v1;
        }
    }
}

// ---------------------------------------------------------------------------
// Rescale + zero-fill wei. Row t: attn wrote cols [0, ((t>>6)+1)*64);
// scale that region by 1/l, zero the rest of the 1024 cols.
// Grid (Tq/2, BHq), 256 threads: 2 rows/block, 128 threads/row.
// ---------------------------------------------------------------------------
__global__ __launch_bounds__(256) void rescale_wei(float* __restrict__ wei) {
    const int bh = blockIdx.y;
    const int t  = blockIdx.x * 2 + (threadIdx.x >> 7);
    const int ln = threadIdx.x & 127;
    const float inv = g_invl[(size_t)bh * Tq + t];
    float4* row = (float4*)(wei + (size_t)bh * Tq * Tq + (size_t)t * Tq);
    const int n4c = ((t >> 6) + 1) * 16;   // written float4s (64-granular causal)
#pragma unroll 2
    for (int w = ln; w < n4c; w += 128) {
        float4 v = row[w];
        v.x *= inv; v.y *= inv; v.z *= inv; v.w *= inv;
        row[w] = v;
    }
    const float4 z = {0.f, 0.f, 0.f, 0.f};
#pragma unroll 2
    for (int w = n4c + ln; w < 256; w += 128) {
        row[w] = z;
    }
}

// ---------------------------------------------------------------------------
// Launch
// ---------------------------------------------------------------------------
extern "C" void kernel_launch(void* const* d_in, const int* in_sizes, int n_in,
                              void* d_out, int out_size) {
    const float* x     = (const float*)d_in[0];
    const float* Wq    = (const float*)d_in[1];
    const float* Wk    = (const float*)d_in[2];
    const float* Wv    = (const float*)d_in[3];
    const float* Wproj = (const float*)d_in[4];
    const float* bproj = (const float*)d_in[5];

    float* out = (float*)d_out;                       // [B,T,C]
    float* wei = out + (size_t)Bq * Tq * Cq;          // [B,H,T,T]

    float *pq, *pk, *pv, *pctx, *pwqkv, *pwp;
    cudaGetSymbolAddress((void**)&pq,    g_q);
    cudaGetSymbolAddress((void**)&pk,    g_k);
    cudaGetSymbolAddress((void**)&pv,    g_v);
    cudaGetSymbolAddress((void**)&pctx,  g_ctx);
    cudaGetSymbolAddress((void**)&pwqkv, g_wqkv);
    cudaGetSymbolAddress((void**)&pwp,   g_wp);

    const int attn_smem = ATTN_SMEM_FLOATS * 4;
    cudaFuncSetAttribute(attn_fused, cudaFuncAttributeMaxDynamicSharedMemorySize, attn_smem);
    cudaFuncSetAttribute(gemm_qkv,  cudaFuncAttributeMaxDynamicSharedMemorySize, GEMM_SMEM_BYTES);
    cudaFuncSetAttribute(gemm_proj, cudaFuncAttributeMaxDynamicSharedMemorySize, GEMM_SMEM_BYTES);

    // 1) weight repack / rounding
    dim3 gw((Cq * Cq) / 256, 3);
    conv_wqkv3_kernel<<<gw, 256>>>(Wq, Wk, Wv, pwqkv);
    conv_wp_kernel<<<(Cq * Cq / 4) / 256, 256>>>((const float4*)Wproj, (float4*)pwp);

    // 2) Q/K/V projections (reads raw x; rounds at fragment read)
    dim3 gqkv(Cq / 128, Mq / 128, 3);
    gemm_qkv<<<gqkv, 256, GEMM_SMEM_BYTES>>>(x, pwqkv, pq, pk, pv);

    // 3) fused one-pass attention (wei unnormalized, causal tiles only)
    dim3 gattn(Tq / 128, BHq);
    attn_fused<<<gattn, 256, attn_smem>>>(wei);

    // 4) normalize + zero-fill wei rows
    dim3 grs(Tq / 2, BHq);
    rescale_wei<<<grs, 256>>>(wei);

    // 5) out = ctx @ Wproj^T + b (in-register 2-term split, K=1024)
    dim3 gout(Cq / 128, Mq / 128);
    gemm_proj<<<gout, 256, GEMM_SMEM_BYTES>>>(pctx, pwp, out, bproj);
}

// round 14
// speedup vs baseline: 1.0011x; 1.0011x over previous
#include <cuda_runtime.h>
#include <math.h>
#include <stdint.h>

// Problem constants
#define Bq 8
#define Tq 1024
#define Cq 1024
#define Hq 16
#define Dq 64
#define Mq (Bq * Tq)          // 8192 rows
#define BHq (Bq * Hq)         // 128

// ---------------------------------------------------------------------------
// Scratch (device globals; no dynamic allocation allowed)
// ---------------------------------------------------------------------------
__device__ float g_q[(size_t)BHq * Tq * Dq];      // [B,H,T,D]  32 MB
__device__ float g_k[(size_t)BHq * Tq * Dq];      // 32 MB
__device__ float g_v[(size_t)BHq * Tq * Dq];      // 32 MB
__device__ float g_ctx[(size_t)Mq * Cq];          // [B,T,C] fp32  32 MB
__device__ float g_wqkv[(size_t)3 * Cq * Cq];     // packed [3][N=HD][K=C] tf32
__device__ float g_wp[(size_t)Cq * Cq];           // Wproj tf32 [N,K]  4 MB
__device__ float g_invl[(size_t)BHq * Tq];        // 1/rowsum per (bh,t)

__device__ __forceinline__ float f2tf32(float a) {
    uint32_t r;
    asm("cvt.rna.tf32.f32 %0, %1;" : "=r"(r) : "f"(a));
    return __uint_as_float(r);
}
__device__ __forceinline__ uint32_t smem_u32(const void* p) {
    uint32_t a;
    asm("{ .reg .u64 t; cvta.to.shared.u64 t, %1; cvt.u32.u64 %0, t; }" : "=r"(a) : "l"(p));
    return a;
}

// ---------------------------------------------------------------------------
// Conversion / repack kernel: z=0..2 -> Wq/Wk/Wv [H,C,D] -> [3][N,K] tf32;
// z=3 -> Wproj elementwise tf32.
// ---------------------------------------------------------------------------
__global__ void conv_w_kernel(const float* __restrict__ Wq,
                              const float* __restrict__ Wk,
                              const float* __restrict__ Wv,
                              const float* __restrict__ Wp,
                              float* __restrict__ Pqkv,
                              float* __restrict__ Pwp) {
    int i = blockIdx.x * blockDim.x + threadIdx.x;
    int z = blockIdx.y;
    if (z < 3) {
        const float* W = (z == 0) ? Wq : (z == 1) ? Wk : Wv;
        int n = i >> 10;
        int c = i & 1023;
        int h = n >> 6, d = n & 63;
        Pqkv[(size_t)z * Cq * Cq + (size_t)n * Cq + c] = f2tf32(W[((size_t)h * Cq + c) * Dq + d]);
    } else {
        Pwp[i] = f2tf32(Wp[i]);
    }
}

// ---------------------------------------------------------------------------
// mma helper
// ---------------------------------------------------------------------------
__device__ __forceinline__ void mma_tf32(float c[4], uint32_t a0, uint32_t a1,
                                         uint32_t a2, uint32_t a3,
                                         uint32_t b0, uint32_t b1) {
    asm volatile(
        "mma.sync.aligned.m16n8k8.row.col.f32.tf32.tf32.f32 "
        "{%0,%1,%2,%3}, {%4,%5,%6,%7}, {%8,%9}, {%0,%1,%2,%3};"
        : "+f"(c[0]), "+f"(c[1]), "+f"(c[2]), "+f"(c[3])
        : "r"(a0), "r"(a1), "r"(a2), "r"(a3), "r"(b0), "r"(b1));
}

// ---------------------------------------------------------------------------
// Shared GEMM plumbing: CTA tile 128x128, K-chunk 32, 3-stage cp.async,
// 256 threads (8 warps 4x2, warp tile 32x64). A[M,K], B[N,K] row-major.
// ---------------------------------------------------------------------------
#define GST 36
#define STGF (2 * 128 * GST)               // floats per stage (A + B)
#define GEMM_SMEM_BYTES (3 * STGF * 4)     // 110592 B

#define GEMM_PRELUDE(Asrc, Bsrc, Ktot)                                          \
    const int tid  = threadIdx.x;                                               \
    const int wid  = tid >> 5;                                                  \
    const int lane = tid & 31;                                                  \
    const int row0 = blockIdx.y * 128;                                          \
    const int col0 = blockIdx.x * 128;                                          \
    const int wm   = (wid & 3) * 32;                                            \
    const int wn   = (wid >> 2) * 64;                                           \
    const uint32_t smb = smem_u32(smem);                                        \
    int lrow[4], lc4[4];                                                        \
    _Pragma("unroll")                                                           \
    for (int l = 0; l < 4; l++) {                                               \
        int idx = l * 256 + tid;                                                \
        lrow[l] = idx >> 3;                                                     \
        lc4[l]  = (idx & 7) << 2;                                               \
    }                                                                           \
    const int NC = (Ktot) >> 5;

#define ISSUE_STAGE(s, buf, Asrc, Bsrc, Ktot)                                   \
    do {                                                                        \
        const int k0 = (s) << 5;                                                \
        const uint32_t sb = smb + (uint32_t)(buf) * (STGF * 4);                 \
        _Pragma("unroll")                                                       \
        for (int l = 0; l < 4; l++) {                                           \
            uint32_t da = sb + (uint32_t)(lrow[l] * GST + lc4[l]) * 4;          \
            const float* sa = (Asrc) + (size_t)(row0 + lrow[l]) * (Ktot) + k0 + lc4[l]; \
            asm volatile("cp.async.cg.shared.global [%0], [%1], 16;"            \
                         :: "r"(da), "l"(sa));                                  \
            uint32_t db = sb + (uint32_t)(128 * GST + lrow[l] * GST + lc4[l]) * 4; \
            const float* sbp = (Bsrc) + (size_t)(col0 + lrow[l]) * (Ktot) + k0 + lc4[l]; \
            asm volatile("cp.async.cg.shared.global [%0], [%1], 16;"            \
                         :: "r"(db), "l"(sbp));                                 \
        }                                                                       \
        asm volatile("cp.async.commit_group;");                                 \
    } while (0)

#define LOAD_B_FRAGS(Bs_, kb)                                                   \
    uint32_t bf[8][2];                                                          \
    {                                                                           \
        const int brow = wn + (lane >> 2);                                      \
        const int bcol = (kb) + (lane & 3);                                     \
        _Pragma("unroll")                                                       \
        for (int nt = 0; nt < 8; nt++) {                                        \
            bf[nt][0] = __float_as_uint(Bs_[(brow + nt * 8) * GST + bcol    ]); \
            bf[nt][1] = __float_as_uint(Bs_[(brow + nt * 8) * GST + bcol + 4]); \
        }                                                                       \
    }

// ---------------------------------------------------------------------------
// QKV GEMM: A = raw x (tf32-rounded at fragment read), B = pre-rounded W.
// grid (8, 64, 3); scatter epilogue into [B,H,T,D].
// ---------------------------------------------------------------------------
__global__ __launch_bounds__(256) void gemm_qkv(
    const float* __restrict__ A, const float* __restrict__ BwBase,
    float* __restrict__ O0, float* __restrict__ O1, float* __restrict__ O2)
{
    extern __shared__ float smem[];
    const float* Bw = BwBase + (size_t)blockIdx.z * Cq * Cq;
    float* Cout = (blockIdx.z == 0) ? O0 : (blockIdx.z == 1) ? O1 : O2;

    GEMM_PRELUDE(A, Bw, Cq)

    float acc[2][8][4];
#pragma unroll
    for (int mt = 0; mt < 2; mt++)
#pragma unroll
        for (int nt = 0; nt < 8; nt++)
#pragma unroll
            for (int j = 0; j < 4; j++) acc[mt][nt][j] = 0.f;

    ISSUE_STAGE(0, 0, A, Bw, Cq);
    ISSUE_STAGE(1, 1, A, Bw, Cq);
    ISSUE_STAGE(2, 2, A, Bw, Cq);

    int cur = 0;
    for (int i = 0; i < NC; i++) {
        asm volatile("cp.async.wait_group 2;");
        __syncthreads();

        const float* As_ = smem + cur * STGF;
        const float* Bs_ = As_ + 128 * GST;

#pragma unroll
        for (int ks = 0; ks < 4; ks++) {
            const int kb = ks * 8;
            const int arow = wm + (lane >> 2);
            const int acol = kb + (lane & 3);
            uint32_t af[2][4];
#pragma unroll
            for (int mt = 0; mt < 2; mt++) {
                af[mt][0] = __float_as_uint(f2tf32(As_[(arow + mt * 16    ) * GST + acol    ]));
                af[mt][1] = __float_as_uint(f2tf32(As_[(arow + mt * 16 + 8) * GST + acol    ]));
                af[mt][2] = __float_as_uint(f2tf32(As_[(arow + mt * 16    ) * GST + acol + 4]));
                af[mt][3] = __float_as_uint(f2tf32(As_[(arow + mt * 16 + 8) * GST + acol + 4]));
            }
            LOAD_B_FRAGS(Bs_, kb)
#pragma unroll
            for (int mt = 0; mt < 2; mt++)
#pragma unroll
                for (int nt = 0; nt < 8; nt++)
                    mma_tf32(acc[mt][nt], af[mt][0], af[mt][1], af[mt][2], af[mt][3],
                             bf[nt][0], bf[nt][1]);
        }
        __syncthreads();

        if (i + 3 < NC) ISSUE_STAGE(i + 3, cur, A, Bw, Cq);
        else asm volatile("cp.async.commit_group;");
        cur = (cur == 2) ? 0 : cur + 1;
    }

    const int er = lane >> 2;
    const int ec = (lane & 3) << 1;
#pragma unroll
    for (int mt = 0; mt < 2; mt++) {
#pragma unroll
        for (int nt = 0; nt < 8; nt++) {
#pragma unroll
            for (int half = 0; half < 2; half++) {
                int m = row0 + wm + mt * 16 + er + half * 8;
                int b = m >> 10, t = m & 1023;
                int n = col0 + wn + nt * 8 + ec;
                int h = n >> 6, d = n & 63;
                float2 v = make_float2(acc[mt][nt][half * 2], acc[mt][nt][half * 2 + 1]);
                *(float2*)(Cout + ((size_t)(b * Hq + h) << 16) + ((size_t)t << 6) + d) = v;
            }
        }
    }
}

// ---------------------------------------------------------------------------
// Proj GEMM: A = raw fp32 ctx; in-register 2-term tf32 split (hi+lo), B = tf32
// Wproj. out[m,n] = sum ctx[m,k] W[n,k] + bias[n]. grid (8, 64).
// ---------------------------------------------------------------------------
__global__ __launch_bounds__(256) void gemm_proj(
    const float* __restrict__ A, const float* __restrict__ Bw,
    float* __restrict__ Cout, const float* __restrict__ bias)
{
    extern __shared__ float smem[];

    GEMM_PRELUDE(A, Bw, Cq)

    float acc[2][8][4];
#pragma unroll
    for (int mt = 0; mt < 2; mt++)
#pragma unroll
        for (int nt = 0; nt < 8; nt++)
#pragma unroll
            for (int j = 0; j < 4; j++) acc[mt][nt][j] = 0.f;

    ISSUE_STAGE(0, 0, A, Bw, Cq);
    ISSUE_STAGE(1, 1, A, Bw, Cq);
    ISSUE_STAGE(2, 2, A, Bw, Cq);

    int cur = 0;
    for (int i = 0; i < NC; i++) {
        asm volatile("cp.async.wait_group 2;");
        __syncthreads();

        const float* As_ = smem + cur * STGF;
        const float* Bs_ = As_ + 128 * GST;

#pragma unroll
        for (int ks = 0; ks < 4; ks++) {
            const int kb = ks * 8;
            const int arow = wm + (lane >> 2);
            const int acol = kb + (lane & 3);
            uint32_t ah[2][4], al[2][4];
#pragma unroll
            for (int mt = 0; mt < 2; mt++) {
                float r0 = As_[(arow + mt * 16    ) * GST + acol    ];
                float r1 = As_[(arow + mt * 16 + 8) * GST + acol    ];
                float r2 = As_[(arow + mt * 16    ) * GST + acol + 4];
                float r3 = As_[(arow + mt * 16 + 8) * GST + acol + 4];
                float h0 = f2tf32(r0), h1 = f2tf32(r1), h2 = f2tf32(r2), h3 = f2tf32(r3);
                ah[mt][0] = __float_as_uint(h0); al[mt][0] = __float_as_uint(f2tf32(r0 - h0));
                ah[mt][1] = __float_as_uint(h1); al[mt][1] = __float_as_uint(f2tf32(r1 - h1));
                ah[mt][2] = __float_as_uint(h2); al[mt][2] = __float_as_uint(f2tf32(r2 - h2));
                ah[mt][3] = __float_as_uint(h3); al[mt][3] = __float_as_uint(f2tf32(r3 - h3));
            }
            LOAD_B_FRAGS(Bs_, kb)
#pragma unroll
            for (int mt = 0; mt < 2; mt++)
#pragma unroll
                for (int nt = 0; nt < 8; nt++) {
                    mma_tf32(acc[mt][nt], ah[mt][0], ah[mt][1], ah[mt][2], ah[mt][3],
                             bf[nt][0], bf[nt][1]);
                    mma_tf32(acc[mt][nt], al[mt][0], al[mt][1], al[mt][2], al[mt][3],
                             bf[nt][0], bf[nt][1]);
                }
        }
        __syncthreads();

        if (i + 3 < NC) ISSUE_STAGE(i + 3, cur, A, Bw, Cq);
        else asm volatile("cp.async.commit_group;");
        cur = (cur == 2) ? 0 : cur + 1;
    }

    const int er = lane >> 2;
    const int ec = (lane & 3) << 1;
#pragma unroll
    for (int mt = 0; mt < 2; mt++) {
#pragma unroll
        for (int nt = 0; nt < 8; nt++) {
#pragma unroll
            for (int half = 0; half < 2; half++) {
                int m = row0 + wm + mt * 16 + er + half * 8;
                int n = col0 + wn + nt * 8 + ec;
                float2 v = make_float2(acc[mt][nt][half * 2] + bias[n],
                                       acc[mt][nt][half * 2 + 1] + bias[n + 1]);
                *(float2*)(Cout + (size_t)m * Cq + n) = v;
            }
        }
    }
}

// ---------------------------------------------------------------------------
// Fused attention, one pass, no-max softmax. K/V double-buffered via cp.async
// (raw fp32 in smem; rna rounding applied at fragment read). Writes
// UNNORMALIZED E=exp(S) to wei (causal 64-granular tiles only; warps 0-3 skip
// fully-masked tile sT=2tB+1). rescale_wei normalizes + zero-fills.
// ctx = (E·V)/l fp32 to g_ctx.
// ---------------------------------------------------------------------------
#define AST 72
#define KVTILE (64 * AST)                              // floats per K or V buffer
#define ATTN_SMEM_FLOATS (128 * AST + 2 * KVTILE + 2 * KVTILE + 128 * AST)

__global__ __launch_bounds__(256, 1) void attn_fused(float* __restrict__ wei) {
    extern __shared__ float sm[];
    float* Qs  = sm;
    float* KsB = Qs + 128 * AST;          // [2][KVTILE]
    float* VsB = KsB + 2 * KVTILE;        // [2][KVTILE]
    float* Ps  = VsB + 2 * KVTILE;

    const int tid  = threadIdx.x;
    const int wid  = tid >> 5;
    const int lane = tid & 31;
    const int tB   = blockIdx.x;
    const int bh   = blockIdx.y;
    const int wm   = wid * 16;
    const int trow0 = tB * 128 + wm + (lane >> 2);
    const int trow1 = trow0 + 8;

    const float* qb = g_q + (size_t)bh * Tq * Dq + (size_t)tB * 128 * Dq;
    const float* kb = g_k + (size_t)bh * Tq * Dq;
    const float* vb = g_v + (size_t)bh * Tq * Dq;
    float* wb = wei + (size_t)bh * Tq * Tq + (size_t)tB * 128 * Tq;

    const uint32_t smb = smem_u32(sm);
    const uint32_t ksb = smb + (uint32_t)(128 * AST) * 4;
    const uint32_t vsb = ksb + (uint32_t)(2 * KVTILE) * 4;

    // cp.async K/V tile loader: 64x64 floats each = 1024 float4; 4 per thread
#define ISSUE_KV(s_, buf_)                                                       \
    do {                                                                         \
        const float* kg = kb + (size_t)((s_) * 64) * Dq;                         \
        const float* vg = vb + (size_t)((s_) * 64) * Dq;                         \
        const uint32_t kd = ksb + (uint32_t)(buf_) * (KVTILE * 4);               \
        const uint32_t vd = vsb + (uint32_t)(buf_) * (KVTILE * 4);               \
        _Pragma("unroll")                                                        \
        for (int l2 = 0; l2 < 4; l2++) {                                         \
            int idx = tid + l2 * 256;                                            \
            int r2 = idx >> 4;                                                   \
            int c2 = (idx & 15) << 2;                                            \
            uint32_t off = (uint32_t)(r2 * AST + c2) * 4;                        \
            asm volatile("cp.async.cg.shared.global [%0], [%1], 16;"             \
                         :: "r"(kd + off), "l"(kg + r2 * Dq + c2));              \
            asm volatile("cp.async.cg.shared.global [%0], [%1], 16;"             \
                         :: "r"(vd + off), "l"(vg + r2 * Dq + c2));              \
        }                                                                        \
        asm volatile("cp.async.commit_group;");                                  \
    } while (0)

    // load Q tile (tf32-rounded, once)
#pragma unroll
    for (int l = 0; l < 8; l++) {
        int f = tid + l * 256;
        int r = f >> 4, c4 = (f & 15) << 2;
        float4 v = *(const float4*)(qb + (size_t)r * Dq + c4);
        Qs[r * AST + c4 + 0] = f2tf32(v.x);
        Qs[r * AST + c4 + 1] = f2tf32(v.y);
        Qs[r * AST + c4 + 2] = f2tf32(v.z);
        Qs[r * AST + c4 + 3] = f2tf32(v.w);
    }
    ISSUE_KV(0, 0);
    __syncthreads();

    // persistent Q fragments
    uint32_t af[8][4];
    {
        const int arow = wm + (lane >> 2);
#pragma unroll
        for (int ks = 0; ks < 8; ks++) {
            const int acol = ks * 8 + (lane & 3);
            af[ks][0] = __float_as_uint(Qs[(arow    ) * AST + acol    ]);
            af[ks][1] = __float_as_uint(Qs[(arow + 8) * AST + acol    ]);
            af[ks][2] = __float_as_uint(Qs[(arow    ) * AST + acol + 4]);
            af[ks][3] = __float_as_uint(Qs[(arow + 8) * AST + acol + 4]);
        }
    }

    const int nS = 2 * tB + 2;
    float l0 = 0.f, l1 = 0.f;
    float ctx[8][4];
#pragma unroll
    for (int nt = 0; nt < 8; nt++)
        { ctx[nt][0]=0.f; ctx[nt][1]=0.f; ctx[nt][2]=0.f; ctx[nt][3]=0.f; }

    for (int sT = 0; sT < nS; sT++) {
        // issue next tile into the other buffer (consumed 2 iterations ago)
        if (sT + 1 < nS) ISSUE_KV(sT + 1, (sT + 1) & 1);
        else asm volatile("cp.async.commit_group;");
        asm volatile("cp.async.wait_group 1;");
        __syncthreads();

        const float* Ks = KsB + (sT & 1) * KVTILE;
        const float* Vs = VsB + (sT & 1) * KVTILE;

        // warps 0-3 (rows 0-63): tile sT == 2tB+1 fully masked -> skip all
        const bool active = (sT <= 2 * tB) || (wm >= 64);
        if (active) {
            float sacc[8][4];
#pragma unroll
            for (int nt = 0; nt < 8; nt++)
                { sacc[nt][0]=0.f; sacc[nt][1]=0.f; sacc[nt][2]=0.f; sacc[nt][3]=0.f; }
#pragma unroll
            for (int ks = 0; ks < 8; ks++) {
                uint32_t bf[8][2];
#pragma unroll
                for (int nt = 0; nt < 8; nt++) {
                    int srow = nt * 8 + (lane >> 2);
                    int scol = ks * 8 + (lane & 3);
                    bf[nt][0] = __float_as_uint(f2tf32(Ks[srow * AST + scol]));
                    bf[nt][1] = __float_as_uint(f2tf32(Ks[srow * AST + scol + 4]));
                }
#pragma unroll
                for (int nt = 0; nt < 8; nt++)
                    mma_tf32(sacc[nt], af[ks][0], af[ks][1], af[ks][2], af[ks][3],
                             bf[nt][0], bf[nt][1]);
            }

            const bool mask = (sT >= 2 * tB);
            {
                const int pr = wm + (lane >> 2);
                const int pc = (lane & 3) << 1;
#pragma unroll
                for (int nt = 0; nt < 8; nt++) {
                    float s0v = sacc[nt][0] * 0.125f;
                    float s1v = sacc[nt][1] * 0.125f;
                    float s2v = sacc[nt][2] * 0.125f;
                    float s3v = sacc[nt][3] * 0.125f;
                    if (mask) {
                        int s0 = sT * 64 + nt * 8 + ((lane & 3) << 1);
                        if (s0     > trow0) s0v = -INFINITY;
                        if (s0 + 1 > trow0) s1v = -INFINITY;
                        if (s0     > trow1) s2v = -INFINITY;
                        if (s0 + 1 > trow1) s3v = -INFINITY;
                    }
                    float e0 = __expf(s0v), e1 = __expf(s1v);
                    float e2 = __expf(s2v), e3 = __expf(s3v);
                    l0 += e0 + e1;
                    l1 += e2 + e3;
                    Ps[(pr    ) * AST + nt * 8 + pc    ] = e0;
                    Ps[(pr    ) * AST + nt * 8 + pc + 1] = e1;
                    Ps[(pr + 8) * AST + nt * 8 + pc    ] = e2;
                    Ps[(pr + 8) * AST + nt * 8 + pc + 1] = e3;
                }
            }
            __syncwarp();   // Ps rows of this warp written by all its lanes

            // write unnormalized E for this warp's 16 rows:
            // 16 rows x 16 float4 = 256 float4, lane + k*32, k=0..7
#pragma unroll
            for (int k = 0; k < 8; k++) {
                int idx = lane + k * 32;
                int rr = wm + (idx >> 4);
                int cc = (idx & 15) << 2;
                *(float4*)(wb + (size_t)rr * Tq + sT * 64 + cc) =
                    *(const float4*)(Ps + rr * AST + cc);
            }

            // ctx += E·V (P rna-rounded at read; V rna-rounded at read)
#pragma unroll
            for (int ks = 0; ks < 8; ks++) {
                const int arow = wm + (lane >> 2);
                const int acol = ks * 8 + (lane & 3);
                uint32_t ap[4];
                ap[0] = __float_as_uint(f2tf32(Ps[(arow    ) * AST + acol    ]));
                ap[1] = __float_as_uint(f2tf32(Ps[(arow + 8) * AST + acol    ]));
                ap[2] = __float_as_uint(f2tf32(Ps[(arow    ) * AST + acol + 4]));
                ap[3] = __float_as_uint(f2tf32(Ps[(arow + 8) * AST + acol + 4]));
                uint32_t bv[8][2];
#pragma unroll
                for (int nt = 0; nt < 8; nt++) {
                    int vrow = ks * 8 + (lane & 3);
                    int vcol = nt * 8 + (lane >> 2);
                    bv[nt][0] = __float_as_uint(f2tf32(Vs[(vrow    ) * AST + vcol]));
                    bv[nt][1] = __float_as_uint(f2tf32(Vs[(vrow + 4) * AST + vcol]));
                }
#pragma unroll
                for (int nt = 0; nt < 8; nt++)
                    mma_tf32(ctx[nt], ap[0], ap[1], ap[2], ap[3], bv[nt][0], bv[nt][1]);
            }
        }
        __syncthreads();   // all warps done with this K/V buffer before reissue
    }

    l0 += __shfl_xor_sync(0xffffffffu, l0, 1);
    l0 += __shfl_xor_sync(0xffffffffu, l0, 2);
    l1 += __shfl_xor_sync(0xffffffffu, l1, 1);
    l1 += __shfl_xor_sync(0xffffffffu, l1, 2);
    const float inv0 = 1.0f / l0;
    const float inv1 = 1.0f / l1;

    if ((lane & 3) == 0) {
        g_invl[(size_t)bh * Tq + trow0] = inv0;
        g_invl[(size_t)bh * Tq + trow1] = inv1;
    }

    // write normalized ctx fp32 -> g_ctx [B,T,C]
    {
        const int b = bh >> 4, h = bh & 15;
        const int ec = (lane & 3) << 1;
#pragma unroll
        for (int nt = 0; nt < 8; nt++) {
            float2 v0 = {ctx[nt][0] * inv0, ctx[nt][1] * inv0};
            float2 v1 = {ctx[nt][2] * inv1, ctx[nt][3] * inv1};
            int c = h * 64 + nt * 8 + ec;
            *(float2*)(g_ctx + ((size_t)(b * Tq + trow0) << 10) + c) = v0;
            *(float2*)(g_ctx + ((size_t)(b * Tq + trow1) << 10) + c) = v1;
        }
    }
#undef ISSUE_KV
}

// ---------------------------------------------------------------------------
// Rescale + zero-fill wei. Row t: attn wrote cols [0, ((t>>6)+1)*64);
// scale that region by 1/l, zero the rest of the 1024 cols.
// ---------------------------------------------------------------------------
__global__ __launch_bounds__(256) void rescale_wei(float* __restrict__ wei) {
    const int bh = blockIdx.y;
    const int t  = blockIdx.x * 2 + (threadIdx.x >> 7);
    const int ln = threadIdx.x & 127;
    const float inv = g_invl[(size_t)bh * Tq + t];
    float4* row = (float4*)(wei + (size_t)bh * Tq * Tq + (size_t)t * Tq);
    const int n4c = ((t >> 6) + 1) * 16;   // written float4s (64-granular causal)
#pragma unroll 2
    for (int w = ln; w < n4c; w += 128) {
        float4 v = row[w];
        v.x *= inv; v.y *= inv; v.z *= inv; v.w *= inv;
        row[w] = v;
    }
    const float4 z = {0.f, 0.f, 0.f, 0.f};
#pragma unroll 2
    for (int w = n4c + ln; w < 256; w += 128) {
        row[w] = z;
    }
}

// ---------------------------------------------------------------------------
// Launch
// ---------------------------------------------------------------------------
extern "C" void kernel_launch(void* const* d_in, const int* in_sizes, int n_in,
                              void* d_out, int out_size) {
    const float* x     = (const float*)d_in[0];
    const float* Wq    = (const float*)d_in[1];
    const float* Wk    = (const float*)d_in[2];
    const float* Wv    = (const float*)d_in[3];
    const float* Wproj = (const float*)d_in[4];
    const float* bproj = (const float*)d_in[5];

    float* out = (float*)d_out;                       // [B,T,C]
    float* wei = out + (size_t)Bq * Tq * Cq;          // [B,H,T,T]

    float *pq, *pk, *pv, *pctx, *pwqkv, *pwp;
    cudaGetSymbolAddress((void**)&pq,    g_q);
    cudaGetSymbolAddress((void**)&pk,    g_k);
    cudaGetSymbolAddress((void**)&pv,    g_v);
    cudaGetSymbolAddress((void**)&pctx,  g_ctx);
    cudaGetSymbolAddress((void**)&pwqkv, g_wqkv);
    cudaGetSymbolAddress((void**)&pwp,   g_wp);

    const int attn_smem = ATTN_SMEM_FLOATS * 4;
    cudaFuncSetAttribute(attn_fused, cudaFuncAttributeMaxDynamicSharedMemorySize, attn_smem);
    cudaFuncSetAttribute(gemm_qkv,  cudaFuncAttributeMaxDynamicSharedMemorySize, GEMM_SMEM_BYTES);
    cudaFuncSetAttribute(gemm_proj, cudaFuncAttributeMaxDynamicSharedMemorySize, GEMM_SMEM_BYTES);

    // 1) weight repack / rounding (z=0..2: QKV; z=3: Wproj)
    dim3 gw((Cq * Cq) / 256, 4);
    conv_w_kernel<<<gw, 256>>>(Wq, Wk, Wv, Wproj, pwqkv, pwp);

    // 2) Q/K/V projections (reads raw x; rounds at fragment read)
    dim3 gqkv(Cq / 128, Mq / 128, 3);
    gemm_qkv<<<gqkv, 256, GEMM_SMEM_BYTES>>>(x, pwqkv, pq, pk, pv);

    // 3) fused one-pass attention (wei unnormalized, causal tiles only)
    dim3 gattn(Tq / 128, BHq);
    attn_fused<<<gattn, 256, attn_smem>>>(wei);

    // 4) normalize + zero-fill wei rows
    dim3 grs(Tq / 2, BHq);
    rescale_wei<<<grs, 256>>>(wei);

    // 5) out = ctx @ Wproj^T + b (in-register 2-term split, K=1024)
    dim3 gout(Cq / 128, Mq / 128);
    gemm_proj<<<gout, 256, GEMM_SMEM_BYTES>>>(pctx, pwp, out, bproj);
}

// round 15
// speedup vs baseline: 1.0259x; 1.0248x over previous
#include <cuda_runtime.h>
#include <math.h>
#include <stdint.h>

// Problem constants
#define Bq 8
#define Tq 1024
#define Cq 1024
#define Hq 16
#define Dq 64
#define Mq (Bq * Tq)          // 8192 rows
#define BHq (Bq * Hq)         // 128

// ---------------------------------------------------------------------------
// Scratch (device globals; no dynamic allocation allowed)
// ---------------------------------------------------------------------------
__device__ float g_q[(size_t)BHq * Tq * Dq];      // [B,H,T,D]  32 MB
__device__ float g_k[(size_t)BHq * Tq * Dq];      // 32 MB
__device__ float g_v[(size_t)BHq * Tq * Dq];      // 32 MB
__device__ float g_ctx[(size_t)Mq * Cq];          // [B,T,C] fp32  32 MB
__device__ float g_wqkv[(size_t)3 * Cq * Cq];     // packed [3][N=HD][K=C] tf32
__device__ float g_wp[(size_t)Cq * Cq];           // Wproj tf32 [N,K]  4 MB
__device__ float g_invl[(size_t)BHq * Tq];        // 1/rowsum per (bh,t)

__device__ __forceinline__ float f2tf32(float a) {
    uint32_t r;
    asm("cvt.rna.tf32.f32 %0, %1;" : "=r"(r) : "f"(a));
    return __uint_as_float(r);
}
__device__ __forceinline__ uint32_t smem_u32(const void* p) {
    uint32_t a;
    asm("{ .reg .u64 t; cvta.to.shared.u64 t, %1; cvt.u32.u64 %0, t; }" : "=r"(a) : "l"(p));
    return a;
}

// ---------------------------------------------------------------------------
// Conversion / repack kernel: z=0..2 -> Wq/Wk/Wv [H,C,D] -> [3][N,K] tf32;
// z=3 -> Wproj elementwise tf32.
// ---------------------------------------------------------------------------
__global__ void conv_w_kernel(const float* __restrict__ Wq,
                              const float* __restrict__ Wk,
                              const float* __restrict__ Wv,
                              const float* __restrict__ Wp,
                              float* __restrict__ Pqkv,
                              float* __restrict__ Pwp) {
    int i = blockIdx.x * blockDim.x + threadIdx.x;
    int z = blockIdx.y;
    if (z < 3) {
        const float* W = (z == 0) ? Wq : (z == 1) ? Wk : Wv;
        int n = i >> 10;
        int c = i & 1023;
        int h = n >> 6, d = n & 63;
        Pqkv[(size_t)z * Cq * Cq + (size_t)n * Cq + c] = f2tf32(W[((size_t)h * Cq + c) * Dq + d]);
    } else {
        Pwp[i] = f2tf32(Wp[i]);
    }
}

// ---------------------------------------------------------------------------
// mma helper
// ---------------------------------------------------------------------------
__device__ __forceinline__ void mma_tf32(float c[4], uint32_t a0, uint32_t a1,
                                         uint32_t a2, uint32_t a3,
                                         uint32_t b0, uint32_t b1) {
    asm volatile(
        "mma.sync.aligned.m16n8k8.row.col.f32.tf32.tf32.f32 "
        "{%0,%1,%2,%3}, {%4,%5,%6,%7}, {%8,%9}, {%0,%1,%2,%3};"
        : "+f"(c[0]), "+f"(c[1]), "+f"(c[2]), "+f"(c[3])
        : "r"(a0), "r"(a1), "r"(a2), "r"(a3), "r"(b0), "r"(b1));
}

// ---------------------------------------------------------------------------
// Shared GEMM plumbing: CTA tile 128x128, K-chunk 32, 3-stage cp.async,
// 256 threads (8 warps 4x2, warp tile 32x64). A[M,K], B[N,K] row-major.
// ---------------------------------------------------------------------------
#define GST 36
#define STGF (2 * 128 * GST)               // floats per stage (A + B)
#define GEMM_SMEM_BYTES (3 * STGF * 4)     // 110592 B

#define GEMM_PRELUDE(Asrc, Bsrc, Ktot)                                          \
    const int tid  = threadIdx.x;                                               \
    const int wid  = tid >> 5;                                                  \
    const int lane = tid & 31;                                                  \
    const int row0 = blockIdx.y * 128;                                          \
    const int col0 = blockIdx.x * 128;                                          \
    const int wm   = (wid & 3) * 32;                                            \
    const int wn   = (wid >> 2) * 64;                                           \
    const uint32_t smb = smem_u32(smem);                                        \
    int lrow[4], lc4[4];                                                        \
    _Pragma("unroll")                                                           \
    for (int l = 0; l < 4; l++) {                                               \
        int idx = l * 256 + tid;                                                \
        lrow[l] = idx >> 3;                                                     \
        lc4[l]  = (idx & 7) << 2;                                               \
    }                                                                           \
    const int NC = (Ktot) >> 5;

#define ISSUE_STAGE(s, buf, Asrc, Bsrc, Ktot)                                   \
    do {                                                                        \
        const int k0 = (s) << 5;                                                \
        const uint32_t sb = smb + (uint32_t)(buf) * (STGF * 4);                 \
        _Pragma("unroll")                                                       \
        for (int l = 0; l < 4; l++) {                                           \
            uint32_t da = sb + (uint32_t)(lrow[l] * GST + lc4[l]) * 4;          \
            const float* sa = (Asrc) + (size_t)(row0 + lrow[l]) * (Ktot) + k0 + lc4[l]; \
            asm volatile("cp.async.cg.shared.global [%0], [%1], 16;"            \
                         :: "r"(da), "l"(sa));                                  \
            uint32_t db = sb + (uint32_t)(128 * GST + lrow[l] * GST + lc4[l]) * 4; \
            const float* sbp = (Bsrc) + (size_t)(col0 + lrow[l]) * (Ktot) + k0 + lc4[l]; \
            asm volatile("cp.async.cg.shared.global [%0], [%1], 16;"            \
                         :: "r"(db), "l"(sbp));                                 \
        }                                                                       \
        asm volatile("cp.async.commit_group;");                                 \
    } while (0)

#define LOAD_B_FRAGS(Bs_, kb)                                                   \
    uint32_t bf[8][2];                                                          \
    {                                                                           \
        const int brow = wn + (lane >> 2);                                      \
        const int bcol = (kb) + (lane & 3);                                     \
        _Pragma("unroll")                                                       \
        for (int nt = 0; nt < 8; nt++) {                                        \
            bf[nt][0] = __float_as_uint(Bs_[(brow + nt * 8) * GST + bcol    ]); \
            bf[nt][1] = __float_as_uint(Bs_[(brow + nt * 8) * GST + bcol + 4]); \
        }                                                                       \
    }

// ---------------------------------------------------------------------------
// QKV GEMM: A = raw x (tf32-rounded at fragment read), B = pre-rounded W.
// grid (8, 64, 3); scatter epilogue into [B,H,T,D].
// ---------------------------------------------------------------------------
__global__ __launch_bounds__(256) void gemm_qkv(
    const float* __restrict__ A, const float* __restrict__ BwBase,
    float* __restrict__ O0, float* __restrict__ O1, float* __restrict__ O2)
{
    extern __shared__ float smem[];
    const float* Bw = BwBase + (size_t)blockIdx.z * Cq * Cq;
    float* Cout = (blockIdx.z == 0) ? O0 : (blockIdx.z == 1) ? O1 : O2;

    GEMM_PRELUDE(A, Bw, Cq)

    float acc[2][8][4];
#pragma unroll
    for (int mt = 0; mt < 2; mt++)
#pragma unroll
        for (int nt = 0; nt < 8; nt++)
#pragma unroll
            for (int j = 0; j < 4; j++) acc[mt][nt][j] = 0.f;

    ISSUE_STAGE(0, 0, A, Bw, Cq);
    ISSUE_STAGE(1, 1, A, Bw, Cq);
    ISSUE_STAGE(2, 2, A, Bw, Cq);

    int cur = 0;
    for (int i = 0; i < NC; i++) {
        asm volatile("cp.async.wait_group 2;");
        __syncthreads();

        const float* As_ = smem + cur * STGF;
        const float* Bs_ = As_ + 128 * GST;

#pragma unroll
        for (int ks = 0; ks < 4; ks++) {
            const int kb = ks * 8;
            const int arow = wm + (lane >> 2);
            const int acol = kb + (lane & 3);
            uint32_t af[2][4];
#pragma unroll
            for (int mt = 0; mt < 2; mt++) {
                af[mt][0] = __float_as_uint(f2tf32(As_[(arow + mt * 16    ) * GST + acol    ]));
                af[mt][1] = __float_as_uint(f2tf32(As_[(arow + mt * 16 + 8) * GST + acol    ]));
                af[mt][2] = __float_as_uint(f2tf32(As_[(arow + mt * 16    ) * GST + acol + 4]));
                af[mt][3] = __float_as_uint(f2tf32(As_[(arow + mt * 16 + 8) * GST + acol + 4]));
            }
            LOAD_B_FRAGS(Bs_, kb)
#pragma unroll
            for (int mt = 0; mt < 2; mt++)
#pragma unroll
                for (int nt = 0; nt < 8; nt++)
                    mma_tf32(acc[mt][nt], af[mt][0], af[mt][1], af[mt][2], af[mt][3],
                             bf[nt][0], bf[nt][1]);
        }
        __syncthreads();

        if (i + 3 < NC) ISSUE_STAGE(i + 3, cur, A, Bw, Cq);
        else asm volatile("cp.async.commit_group;");
        cur = (cur == 2) ? 0 : cur + 1;
    }

    const int er = lane >> 2;
    const int ec = (lane & 3) << 1;
#pragma unroll
    for (int mt = 0; mt < 2; mt++) {
#pragma unroll
        for (int nt = 0; nt < 8; nt++) {
#pragma unroll
            for (int half = 0; half < 2; half++) {
                int m = row0 + wm + mt * 16 + er + half * 8;
                int b = m >> 10, t = m & 1023;
                int n = col0 + wn + nt * 8 + ec;
                int h = n >> 6, d = n & 63;
                float2 v = make_float2(acc[mt][nt][half * 2], acc[mt][nt][half * 2 + 1]);
                *(float2*)(Cout + ((size_t)(b * Hq + h) << 16) + ((size_t)t << 6) + d) = v;
            }
        }
    }
}

// ---------------------------------------------------------------------------
// Proj GEMM: A = raw fp32 ctx; in-register 2-term tf32 split (hi+lo), B = tf32
// Wproj. out[m,n] = sum ctx[m,k] W[n,k] + bias[n]. grid (8, 64).
// ---------------------------------------------------------------------------
__global__ __launch_bounds__(256) void gemm_proj(
    const float* __restrict__ A, const float* __restrict__ Bw,
    float* __restrict__ Cout, const float* __restrict__ bias)
{
    extern __shared__ float smem[];

    GEMM_PRELUDE(A, Bw, Cq)

    float acc[2][8][4];
#pragma unroll
    for (int mt = 0; mt < 2; mt++)
#pragma unroll
        for (int nt = 0; nt < 8; nt++)
#pragma unroll
            for (int j = 0; j < 4; j++) acc[mt][nt][j] = 0.f;

    ISSUE_STAGE(0, 0, A, Bw, Cq);
    ISSUE_STAGE(1, 1, A, Bw, Cq);
    ISSUE_STAGE(2, 2, A, Bw, Cq);

    int cur = 0;
    for (int i = 0; i < NC; i++) {
        asm volatile("cp.async.wait_group 2;");
        __syncthreads();

        const float* As_ = smem + cur * STGF;
        const float* Bs_ = As_ + 128 * GST;

#pragma unroll
        for (int ks = 0; ks < 4; ks++) {
            const int kb = ks * 8;
            const int arow = wm + (lane >> 2);
            const int acol = kb + (lane & 3);
            uint32_t ah[2][4], al[2][4];
#pragma unroll
            for (int mt = 0; mt < 2; mt++) {
                float r0 = As_[(arow + mt * 16    ) * GST + acol    ];
                float r1 = As_[(arow + mt * 16 + 8) * GST + acol    ];
                float r2 = As_[(arow + mt * 16    ) * GST + acol + 4];
                float r3 = As_[(arow + mt * 16 + 8) * GST + acol + 4];
                float h0 = f2tf32(r0), h1 = f2tf32(r1), h2 = f2tf32(r2), h3 = f2tf32(r3);
                ah[mt][0] = __float_as_uint(h0); al[mt][0] = __float_as_uint(f2tf32(r0 - h0));
                ah[mt][1] = __float_as_uint(h1); al[mt][1] = __float_as_uint(f2tf32(r1 - h1));
                ah[mt][2] = __float_as_uint(h2); al[mt][2] = __float_as_uint(f2tf32(r2 - h2));
                ah[mt][3] = __float_as_uint(h3); al[mt][3] = __float_as_uint(f2tf32(r3 - h3));
            }
            LOAD_B_FRAGS(Bs_, kb)
#pragma unroll
            for (int mt = 0; mt < 2; mt++)
#pragma unroll
                for (int nt = 0; nt < 8; nt++) {
                    mma_tf32(acc[mt][nt], ah[mt][0], ah[mt][1], ah[mt][2], ah[mt][3],
                             bf[nt][0], bf[nt][1]);
                    mma_tf32(acc[mt][nt], al[mt][0], al[mt][1], al[mt][2], al[mt][3],
                             bf[nt][0], bf[nt][1]);
                }
        }
        __syncthreads();

        if (i + 3 < NC) ISSUE_STAGE(i + 3, cur, A, Bw, Cq);
        else asm volatile("cp.async.commit_group;");
        cur = (cur == 2) ? 0 : cur + 1;
    }

    const int er = lane >> 2;
    const int ec = (lane & 3) << 1;
#pragma unroll
    for (int mt = 0; mt < 2; mt++) {
#pragma unroll
        for (int nt = 0; nt < 8; nt++) {
#pragma unroll
            for (int half = 0; half < 2; half++) {
                int m = row0 + wm + mt * 16 + er + half * 8;
                int n = col0 + wn + nt * 8 + ec;
                float2 v = make_float2(acc[mt][nt][half * 2] + bias[n],
                                       acc[mt][nt][half * 2 + 1] + bias[n + 1]);
                *(float2*)(Cout + (size_t)m * Cq + n) = v;
            }
        }
    }
}

// ---------------------------------------------------------------------------
// Fused attention, 64-row t-blocks, 128 threads (4 warps x 16 rows).
// One pass, no-max softmax. K/V double-buffered via cp.async (raw fp32 in
// smem; rna rounding at fragment read). Writes UNNORMALIZED E=exp(S) to wei
// (causal 64-granular tiles, sT = 0..tB). rescale_wei normalizes+zero-fills.
// ctx = (E·V)/l fp32 to g_ctx. 108KB smem + ~200 regs -> 2 CTAs/SM.
// ---------------------------------------------------------------------------
#define AST 72
#define KVTILE (64 * AST)                              // floats per K or V buffer
#define ATTN_SMEM_FLOATS (64 * AST + 2 * KVTILE + 2 * KVTILE + 64 * AST)

__global__ __launch_bounds__(128, 2) void attn_fused(float* __restrict__ wei) {
    extern __shared__ float sm[];
    float* Qs  = sm;                      // [64][AST]
    float* KsB = Qs + 64 * AST;           // [2][KVTILE]
    float* VsB = KsB + 2 * KVTILE;        // [2][KVTILE]
    float* Ps  = VsB + 2 * KVTILE;        // [64][AST]

    const int tid  = threadIdx.x;
    const int wid  = tid >> 5;
    const int lane = tid & 31;
    const int tB   = blockIdx.x;          // 64-row t-block, 0..15
    const int bh   = blockIdx.y;
    const int wm   = wid * 16;            // warp row offset within 64-row block
    const int trow0 = tB * 64 + wm + (lane >> 2);
    const int trow1 = trow0 + 8;

    const float* qb = g_q + (size_t)bh * Tq * Dq + (size_t)tB * 64 * Dq;
    const float* kb = g_k + (size_t)bh * Tq * Dq;
    const float* vb = g_v + (size_t)bh * Tq * Dq;
    float* wb = wei + (size_t)bh * Tq * Tq + (size_t)tB * 64 * Tq;

    const uint32_t smb = smem_u32(sm);
    const uint32_t ksb = smb + (uint32_t)(64 * AST) * 4;
    const uint32_t vsb = ksb + (uint32_t)(2 * KVTILE) * 4;

    // cp.async K/V tile loader: 64x64 floats each = 1024 float4; 8 per thread
#define ISSUE_KV(s_, buf_)                                                       \
    do {                                                                         \
        const float* kg = kb + (size_t)((s_) * 64) * Dq;                         \
        const float* vg = vb + (size_t)((s_) * 64) * Dq;                         \
        const uint32_t kd = ksb + (uint32_t)(buf_) * (KVTILE * 4);               \
        const uint32_t vd = vsb + (uint32_t)(buf_) * (KVTILE * 4);               \
        _Pragma("unroll")                                                        \
        for (int l2 = 0; l2 < 8; l2++) {                                         \
            int idx = tid + l2 * 128;                                            \
            int r2 = idx >> 4;                                                   \
            int c2 = (idx & 15) << 2;                                            \
            uint32_t off = (uint32_t)(r2 * AST + c2) * 4;                        \
            asm volatile("cp.async.cg.shared.global [%0], [%1], 16;"             \
                         :: "r"(kd + off), "l"(kg + r2 * Dq + c2));              \
            asm volatile("cp.async.cg.shared.global [%0], [%1], 16;"             \
                         :: "r"(vd + off), "l"(vg + r2 * Dq + c2));              \
        }                                                                        \
        asm volatile("cp.async.commit_group;");                                  \
    } while (0)

    // load Q tile (tf32-rounded, once): 64 rows x 16 float4 = 1024 / 128 = 8 ea
#pragma unroll
    for (int l = 0; l < 8; l++) {
        int f = tid + l * 128;
        int r = f >> 4, c4 = (f & 15) << 2;
        float4 v = *(const float4*)(qb + (size_t)r * Dq + c4);
        Qs[r * AST + c4 + 0] = f2tf32(v.x);
        Qs[r * AST + c4 + 1] = f2tf32(v.y);
        Qs[r * AST + c4 + 2] = f2tf32(v.z);
        Qs[r * AST + c4 + 3] = f2tf32(v.w);
    }
    ISSUE_KV(0, 0);
    __syncthreads();

    // persistent Q fragments
    uint32_t af[8][4];
    {
        const int arow = wm + (lane >> 2);
#pragma unroll
        for (int ks = 0; ks < 8; ks++) {
            const int acol = ks * 8 + (lane & 3);
            af[ks][0] = __float_as_uint(Qs[(arow    ) * AST + acol    ]);
            af[ks][1] = __float_as_uint(Qs[(arow + 8) * AST + acol    ]);
            af[ks][2] = __float_as_uint(Qs[(arow    ) * AST + acol + 4]);
            af[ks][3] = __float_as_uint(Qs[(arow + 8) * AST + acol + 4]);
        }
    }

    const int nS = tB + 1;                 // tiles 0..tB (tB is the diagonal)
    float l0 = 0.f, l1 = 0.f;
    float ctx[8][4];
#pragma unroll
    for (int nt = 0; nt < 8; nt++)
        { ctx[nt][0]=0.f; ctx[nt][1]=0.f; ctx[nt][2]=0.f; ctx[nt][3]=0.f; }

    for (int sT = 0; sT < nS; sT++) {
        if (sT + 1 < nS) ISSUE_KV(sT + 1, (sT + 1) & 1);
        else asm volatile("cp.async.commit_group;");
        asm volatile("cp.async.wait_group 1;");
        __syncthreads();

        const float* Ks = KsB + (sT & 1) * KVTILE;
        const float* Vs = VsB + (sT & 1) * KVTILE;

        // S = Q·K^T
        float sacc[8][4];
#pragma unroll
        for (int nt = 0; nt < 8; nt++)
            { sacc[nt][0]=0.f; sacc[nt][1]=0.f; sacc[nt][2]=0.f; sacc[nt][3]=0.f; }
#pragma unroll
        for (int ks = 0; ks < 8; ks++) {
            uint32_t bf[8][2];
#pragma unroll
            for (int nt = 0; nt < 8; nt++) {
                int srow = nt * 8 + (lane >> 2);
                int scol = ks * 8 + (lane & 3);
                bf[nt][0] = __float_as_uint(f2tf32(Ks[srow * AST + scol]));
                bf[nt][1] = __float_as_uint(f2tf32(Ks[srow * AST + scol + 4]));
            }
#pragma unroll
            for (int nt = 0; nt < 8; nt++)
                mma_tf32(sacc[nt], af[ks][0], af[ks][1], af[ks][2], af[ks][3],
                         bf[nt][0], bf[nt][1]);
        }

        const bool mask = (sT == tB);      // diagonal tile
        {
            const int pr = wm + (lane >> 2);
            const int pc = (lane & 3) << 1;
#pragma unroll
            for (int nt = 0; nt < 8; nt++) {
                float s0v = sacc[nt][0] * 0.125f;
                float s1v = sacc[nt][1] * 0.125f;
                float s2v = sacc[nt][2] * 0.125f;
                float s3v = sacc[nt][3] * 0.125f;
                if (mask) {
                    int s0 = sT * 64 + nt * 8 + ((lane & 3) << 1);
                    if (s0     > trow0) s0v = -INFINITY;
                    if (s0 + 1 > trow0) s1v = -INFINITY;
                    if (s0     > trow1) s2v = -INFINITY;
                    if (s0 + 1 > trow1) s3v = -INFINITY;
                }
                float e0 = __expf(s0v), e1 = __expf(s1v);
                float e2 = __expf(s2v), e3 = __expf(s3v);
                l0 += e0 + e1;
                l1 += e2 + e3;
                Ps[(pr    ) * AST + nt * 8 + pc    ] = e0;
                Ps[(pr    ) * AST + nt * 8 + pc + 1] = e1;
                Ps[(pr + 8) * AST + nt * 8 + pc    ] = e2;
                Ps[(pr + 8) * AST + nt * 8 + pc + 1] = e3;
            }
        }
        __syncwarp();   // this warp's Ps rows complete

        // write unnormalized E for this warp's 16 rows:
        // 16 rows x 16 float4 = 256 float4, lane + k*32, k=0..7
#pragma unroll
        for (int k = 0; k < 8; k++) {
            int idx = lane + k * 32;
            int rr = wm + (idx >> 4);
            int cc = (idx & 15) << 2;
            *(float4*)(wb + (size_t)rr * Tq + sT * 64 + cc) =
                *(const float4*)(Ps + rr * AST + cc);
        }

        // ctx += E·V (P rna-rounded at read; V rna-rounded at read)
#pragma unroll
        for (int ks = 0; ks < 8; ks++) {
            const int arow = wm + (lane >> 2);
            const int acol = ks * 8 + (lane & 3);
            uint32_t ap[4];
            ap[0] = __float_as_uint(f2tf32(Ps[(arow    ) * AST + acol    ]));
            ap[1] = __float_as_uint(f2tf32(Ps[(arow + 8) * AST + acol    ]));
            ap[2] = __float_as_uint(f2tf32(Ps[(arow    ) * AST + acol + 4]));
            ap[3] = __float_as_uint(f2tf32(Ps[(arow + 8) * AST + acol + 4]));
            uint32_t bv[8][2];
#pragma unroll
            for (int nt = 0; nt < 8; nt++) {
                int vrow = ks * 8 + (lane & 3);
                int vcol = nt * 8 + (lane >> 2);
                bv[nt][0] = __float_as_uint(f2tf32(Vs[(vrow    ) * AST + vcol]));
                bv[nt][1] = __float_as_uint(f2tf32(Vs[(vrow + 4) * AST + vcol]));
            }
#pragma unroll
            for (int nt = 0; nt < 8; nt++)
                mma_tf32(ctx[nt], ap[0], ap[1], ap[2], ap[3], bv[nt][0], bv[nt][1]);
        }
        __syncthreads();   // all warps done with this K/V buffer before reissue
    }

    l0 += __shfl_xor_sync(0xffffffffu, l0, 1);
    l0 += __shfl_xor_sync(0xffffffffu, l0, 2);
    l1 += __shfl_xor_sync(0xffffffffu, l1, 1);
    l1 += __shfl_xor_sync(0xffffffffu, l1, 2);
    const float inv0 = 1.0f / l0;
    const float inv1 = 1.0f / l1;

    if ((lane & 3) == 0) {
        g_invl[(size_t)bh * Tq + trow0] = inv0;
        g_invl[(size_t)bh * Tq + trow1] = inv1;
    }

    // write normalized ctx fp32 -> g_ctx [B,T,C]
    {
        const int b = bh >> 4, h = bh & 15;
        const int ec = (lane & 3) << 1;
#pragma unroll
        for (int nt = 0; nt < 8; nt++) {
            float2 v0 = {ctx[nt][0] * inv0, ctx[nt][1] * inv0};
            float2 v1 = {ctx[nt][2] * inv1, ctx[nt][3] * inv1};
            int c = h * 64 + nt * 8 + ec;
            *(float2*)(g_ctx + ((size_t)(b * Tq + trow0) << 10) + c) = v0;
            *(float2*)(g_ctx + ((size_t)(b * Tq + trow1) << 10) + c) = v1;
        }
    }
#undef ISSUE_KV
}

// ---------------------------------------------------------------------------
// Rescale + zero-fill wei. Row t: attn wrote cols [0, ((t>>6)+1)*64);
// scale that region by 1/l, zero the rest of the 1024 cols.
// ---------------------------------------------------------------------------
__global__ __launch_bounds__(256) void rescale_wei(float* __restrict__ wei) {
    const int bh = blockIdx.y;
    const int t  = blockIdx.x * 2 + (threadIdx.x >> 7);
    const int ln = threadIdx.x & 127;
    const float inv = g_invl[(size_t)bh * Tq + t];
    float4* row = (float4*)(wei + (size_t)bh * Tq * Tq + (size_t)t * Tq);
    const int n4c = ((t >> 6) + 1) * 16;   // written float4s (64-granular causal)
#pragma unroll 2
    for (int w = ln; w < n4c; w += 128) {
        float4 v = row[w];
        v.x *= inv; v.y *= inv; v.z *= inv; v.w *= inv;
        row[w] = v;
    }
    const float4 z = {0.f, 0.f, 0.f, 0.f};
#pragma unroll 2
    for (int w = n4c + ln; w < 256; w += 128) {
        row[w] = z;
    }
}

// ---------------------------------------------------------------------------
// Launch
// ---------------------------------------------------------------------------
extern "C" void kernel_launch(void* const* d_in, const int* in_sizes, int n_in,
                              void* d_out, int out_size) {
    const float* x     = (const float*)d_in[0];
    const float* Wq    = (const float*)d_in[1];
    const float* Wk    = (const float*)d_in[2];
    const float* Wv    = (const float*)d_in[3];
    const float* Wproj = (const float*)d_in[4];
    const float* bproj = (const float*)d_in[5];

    float* out = (float*)d_out;                       // [B,T,C]
    float* wei = out + (size_t)Bq * Tq * Cq;          // [B,H,T,T]

    float *pq, *pk, *pv, *pctx, *pwqkv, *pwp;
    cudaGetSymbolAddress((void**)&pq,    g_q);
    cudaGetSymbolAddress((void**)&pk,    g_k);
    cudaGetSymbolAddress((void**)&pv,    g_v);
    cudaGetSymbolAddress((void**)&pctx,  g_ctx);
    cudaGetSymbolAddress((void**)&pwqkv, g_wqkv);
    cudaGetSymbolAddress((void**)&pwp,   g_wp);

    const int attn_smem = ATTN_SMEM_FLOATS * 4;
    cudaFuncSetAttribute(attn_fused, cudaFuncAttributeMaxDynamicSharedMemorySize, attn_smem);
    cudaFuncSetAttribute(gemm_qkv,  cudaFuncAttributeMaxDynamicSharedMemorySize, GEMM_SMEM_BYTES);
    cudaFuncSetAttribute(gemm_proj, cudaFuncAttributeMaxDynamicSharedMemorySize, GEMM_SMEM_BYTES);

    // 1) weight repack / rounding (z=0..2: QKV; z=3: Wproj)
    dim3 gw((Cq * Cq) / 256, 4);
    conv_w_kernel<<<gw, 256>>>(Wq, Wk, Wv, Wproj, pwqkv, pwp);

    // 2) Q/K/V projections (reads raw x; rounds at fragment read)
    dim3 gqkv(Cq / 128, Mq / 128, 3);
    gemm_qkv<<<gqkv, 256, GEMM_SMEM_BYTES>>>(x, pwqkv, pq, pk, pv);

    // 3) fused one-pass attention, 64-row blocks (wei unnormalized, causal only)
    dim3 gattn(Tq / 64, BHq);
    attn_fused<<<gattn, 128, attn_smem>>>(wei);

    // 4) normalize + zero-fill wei rows
    dim3 grs(Tq / 2, BHq);
    rescale_wei<<<grs, 256>>>(wei);

    // 5) out = ctx @ Wproj^T + b (in-register 2-term split, K=1024)
    dim3 gout(Cq / 128, Mq / 128);
    gemm_proj<<<gout, 256, GEMM_SMEM_BYTES>>>(pctx, pwp, out, bproj);
}

// round 16
// speedup vs baseline: 1.0356x; 1.0094x over previous
#include <cuda_runtime.h>
#include <math.h>
#include <stdint.h>

// Problem constants
#define Bq 8
#define Tq 1024
#define Cq 1024
#define Hq 16
#define Dq 64
#define Mq (Bq * Tq)          // 8192 rows
#define BHq (Bq * Hq)         // 128

// ---------------------------------------------------------------------------
// Scratch (device globals; no dynamic allocation allowed)
// ---------------------------------------------------------------------------
__device__ float g_q[(size_t)BHq * Tq * Dq];      // [B,H,T,D]  32 MB
__device__ float g_k[(size_t)BHq * Tq * Dq];      // 32 MB
__device__ float g_v[(size_t)BHq * Tq * Dq];      // 32 MB
__device__ float g_ctx[(size_t)Mq * Cq];          // [B,T,C] fp32  32 MB
__device__ float g_wqkv[(size_t)3 * Cq * Cq];     // packed [3][N=HD][K=C] tf32
__device__ float g_wp[(size_t)Cq * Cq];           // Wproj tf32 [N,K]  4 MB
__device__ float g_invl[(size_t)BHq * Tq];        // 1/rowsum per (bh,t)

__device__ __forceinline__ float f2tf32(float a) {
    uint32_t r;
    asm("cvt.rna.tf32.f32 %0, %1;" : "=r"(r) : "f"(a));
    return __uint_as_float(r);
}
__device__ __forceinline__ uint32_t smem_u32(const void* p) {
    uint32_t a;
    asm("{ .reg .u64 t; cvta.to.shared.u64 t, %1; cvt.u32.u64 %0, t; }" : "=r"(a) : "l"(p));
    return a;
}

// ---------------------------------------------------------------------------
// Conversion / repack kernel: z=0..2 -> Wq/Wk/Wv [H,C,D] -> [3][N,K] tf32;
// z=3 -> Wproj elementwise tf32.
// ---------------------------------------------------------------------------
__global__ void conv_w_kernel(const float* __restrict__ Wq,
                              const float* __restrict__ Wk,
                              const float* __restrict__ Wv,
                              const float* __restrict__ Wp,
                              float* __restrict__ Pqkv,
                              float* __restrict__ Pwp) {
    int i = blockIdx.x * blockDim.x + threadIdx.x;
    int z = blockIdx.y;
    if (z < 3) {
        const float* W = (z == 0) ? Wq : (z == 1) ? Wk : Wv;
        int n = i >> 10;
        int c = i & 1023;
        int h = n >> 6, d = n & 63;
        Pqkv[(size_t)z * Cq * Cq + (size_t)n * Cq + c] = f2tf32(W[((size_t)h * Cq + c) * Dq + d]);
    } else {
        Pwp[i] = f2tf32(Wp[i]);
    }
}

// ---------------------------------------------------------------------------
// mma helper
// ---------------------------------------------------------------------------
__device__ __forceinline__ void mma_tf32(float c[4], uint32_t a0, uint32_t a1,
                                         uint32_t a2, uint32_t a3,
                                         uint32_t b0, uint32_t b1) {
    asm volatile(
        "mma.sync.aligned.m16n8k8.row.col.f32.tf32.tf32.f32 "
        "{%0,%1,%2,%3}, {%4,%5,%6,%7}, {%8,%9}, {%0,%1,%2,%3};"
        : "+f"(c[0]), "+f"(c[1]), "+f"(c[2]), "+f"(c[3])
        : "r"(a0), "r"(a1), "r"(a2), "r"(a3), "r"(b0), "r"(b1));
}

// ---------------------------------------------------------------------------
// Shared GEMM plumbing: CTA tile 128x128, K-chunk 32, 3-buffer cp.async with
// ONE __syncthreads per chunk (issue into buf (i+2)%3, consumed at i-1).
// 256 threads (8 warps 4x2, warp tile 32x64). A[M,K], B[N,K] row-major.
// ---------------------------------------------------------------------------
#define GST 36
#define STGF (2 * 128 * GST)               // floats per stage (A + B)
#define GEMM_SMEM_BYTES (3 * STGF * 4)     // 110592 B

#define GEMM_PRELUDE(Asrc, Bsrc, Ktot)                                          \
    const int tid  = threadIdx.x;                                               \
    const int wid  = tid >> 5;                                                  \
    const int lane = tid & 31;                                                  \
    const int row0 = blockIdx.y * 128;                                          \
    const int col0 = blockIdx.x * 128;                                          \
    const int wm   = (wid & 3) * 32;                                            \
    const int wn   = (wid >> 2) * 64;                                           \
    const uint32_t smb = smem_u32(smem);                                        \
    int lrow[4], lc4[4];                                                        \
    _Pragma("unroll")                                                           \
    for (int l = 0; l < 4; l++) {                                               \
        int idx = l * 256 + tid;                                                \
        lrow[l] = idx >> 3;                                                     \
        lc4[l]  = (idx & 7) << 2;                                               \
    }                                                                           \
    const int NC = (Ktot) >> 5;

#define ISSUE_STAGE(s, buf, Asrc, Bsrc, Ktot)                                   \
    do {                                                                        \
        const int k0 = (s) << 5;                                                \
        const uint32_t sb = smb + (uint32_t)(buf) * (STGF * 4);                 \
        _Pragma("unroll")                                                       \
        for (int l = 0; l < 4; l++) {                                           \
            uint32_t da = sb + (uint32_t)(lrow[l] * GST + lc4[l]) * 4;          \
            const float* sa = (Asrc) + (size_t)(row0 + lrow[l]) * (Ktot) + k0 + lc4[l]; \
            asm volatile("cp.async.cg.shared.global [%0], [%1], 16;"            \
                         :: "r"(da), "l"(sa));                                  \
            uint32_t db = sb + (uint32_t)(128 * GST + lrow[l] * GST + lc4[l]) * 4; \
            const float* sbp = (Bsrc) + (size_t)(col0 + lrow[l]) * (Ktot) + k0 + lc4[l]; \
            asm volatile("cp.async.cg.shared.global [%0], [%1], 16;"            \
                         :: "r"(db), "l"(sbp));                                 \
        }                                                                       \
        asm volatile("cp.async.commit_group;");                                 \
    } while (0)

#define LOAD_B_FRAGS(Bs_, kb)                                                   \
    uint32_t bf[8][2];                                                          \
    {                                                                           \
        const int brow = wn + (lane >> 2);                                      \
        const int bcol = (kb) + (lane & 3);                                     \
        _Pragma("unroll")                                                       \
        for (int nt = 0; nt < 8; nt++) {                                        \
            bf[nt][0] = __float_as_uint(Bs_[(brow + nt * 8) * GST + bcol    ]); \
            bf[nt][1] = __float_as_uint(Bs_[(brow + nt * 8) * GST + bcol + 4]); \
        }                                                                       \
    }

// ---------------------------------------------------------------------------
// QKV GEMM: A = raw x (tf32-rounded at fragment read), B = pre-rounded W.
// grid (8, 64, 3); scatter epilogue into [B,H,T,D].
// ---------------------------------------------------------------------------
__global__ __launch_bounds__(256) void gemm_qkv(
    const float* __restrict__ A, const float* __restrict__ BwBase,
    float* __restrict__ O0, float* __restrict__ O1, float* __restrict__ O2)
{
    extern __shared__ float smem[];
    const float* Bw = BwBase + (size_t)blockIdx.z * Cq * Cq;
    float* Cout = (blockIdx.z == 0) ? O0 : (blockIdx.z == 1) ? O1 : O2;

    GEMM_PRELUDE(A, Bw, Cq)

    float acc[2][8][4];
#pragma unroll
    for (int mt = 0; mt < 2; mt++)
#pragma unroll
        for (int nt = 0; nt < 8; nt++)
#pragma unroll
            for (int j = 0; j < 4; j++) acc[mt][nt][j] = 0.f;

    ISSUE_STAGE(0, 0, A, Bw, Cq);
    ISSUE_STAGE(1, 1, A, Bw, Cq);

    for (int i = 0; i < NC; i++) {
        asm volatile("cp.async.wait_group 1;");   // stage i complete
        __syncthreads();                          // buf (i+2)%3 consumers done

        if (i + 2 < NC) ISSUE_STAGE(i + 2, (i + 2) % 3, A, Bw, Cq);
        else asm volatile("cp.async.commit_group;");

        const float* As_ = smem + (i % 3) * STGF;
        const float* Bs_ = As_ + 128 * GST;

#pragma unroll
        for (int ks = 0; ks < 4; ks++) {
            const int kb = ks * 8;
            const int arow = wm + (lane >> 2);
            const int acol = kb + (lane & 3);
            uint32_t af[2][4];
#pragma unroll
            for (int mt = 0; mt < 2; mt++) {
                af[mt][0] = __float_as_uint(f2tf32(As_[(arow + mt * 16    ) * GST + acol    ]));
                af[mt][1] = __float_as_uint(f2tf32(As_[(arow + mt * 16 + 8) * GST + acol    ]));
                af[mt][2] = __float_as_uint(f2tf32(As_[(arow + mt * 16    ) * GST + acol + 4]));
                af[mt][3] = __float_as_uint(f2tf32(As_[(arow + mt * 16 + 8) * GST + acol + 4]));
            }
            LOAD_B_FRAGS(Bs_, kb)
#pragma unroll
            for (int mt = 0; mt < 2; mt++)
#pragma unroll
                for (int nt = 0; nt < 8; nt++)
                    mma_tf32(acc[mt][nt], af[mt][0], af[mt][1], af[mt][2], af[mt][3],
                             bf[nt][0], bf[nt][1]);
        }
    }

    const int er = lane >> 2;
    const int ec = (lane & 3) << 1;
#pragma unroll
    for (int mt = 0; mt < 2; mt++) {
#pragma unroll
        for (int nt = 0; nt < 8; nt++) {
#pragma unroll
            for (int half = 0; half < 2; half++) {
                int m = row0 + wm + mt * 16 + er + half * 8;
                int b = m >> 10, t = m & 1023;
                int n = col0 + wn + nt * 8 + ec;
                int h = n >> 6, d = n & 63;
                float2 v = make_float2(acc[mt][nt][half * 2], acc[mt][nt][half * 2 + 1]);
                *(float2*)(Cout + ((size_t)(b * Hq + h) << 16) + ((size_t)t << 6) + d) = v;
            }
        }
    }
}

// ---------------------------------------------------------------------------
// Proj GEMM: A = raw fp32 ctx; in-register 2-term tf32 split (hi+lo), B = tf32
// Wproj. out[m,n] = sum ctx[m,k] W[n,k] + bias[n]. grid (8, 64).
// ---------------------------------------------------------------------------
__global__ __launch_bounds__(256) void gemm_proj(
    const float* __restrict__ A, const float* __restrict__ Bw,
    float* __restrict__ Cout, const float* __restrict__ bias)
{
    extern __shared__ float smem[];

    GEMM_PRELUDE(A, Bw, Cq)

    float acc[2][8][4];
#pragma unroll
    for (int mt = 0; mt < 2; mt++)
#pragma unroll
        for (int nt = 0; nt < 8; nt++)
#pragma unroll
            for (int j = 0; j < 4; j++) acc[mt][nt][j] = 0.f;

    ISSUE_STAGE(0, 0, A, Bw, Cq);
    ISSUE_STAGE(1, 1, A, Bw, Cq);

    for (int i = 0; i < NC; i++) {
        asm volatile("cp.async.wait_group 1;");
        __syncthreads();

        if (i + 2 < NC) ISSUE_STAGE(i + 2, (i + 2) % 3, A, Bw, Cq);
        else asm volatile("cp.async.commit_group;");

        const float* As_ = smem + (i % 3) * STGF;
        const float* Bs_ = As_ + 128 * GST;

#pragma unroll
        for (int ks = 0; ks < 4; ks++) {
            const int kb = ks * 8;
            const int arow = wm + (lane >> 2);
            const int acol = kb + (lane & 3);
            uint32_t ah[2][4], al[2][4];
#pragma unroll
            for (int mt = 0; mt < 2; mt++) {
                float r0 = As_[(arow + mt * 16    ) * GST + acol    ];
                float r1 = As_[(arow + mt * 16 + 8) * GST + acol    ];
                float r2 = As_[(arow + mt * 16    ) * GST + acol + 4];
                float r3 = As_[(arow + mt * 16 + 8) * GST + acol + 4];
                float h0 = f2tf32(r0), h1 = f2tf32(r1), h2 = f2tf32(r2), h3 = f2tf32(r3);
                ah[mt][0] = __float_as_uint(h0); al[mt][0] = __float_as_uint(f2tf32(r0 - h0));
                ah[mt][1] = __float_as_uint(h1); al[mt][1] = __float_as_uint(f2tf32(r1 - h1));
                ah[mt][2] = __float_as_uint(h2); al[mt][2] = __float_as_uint(f2tf32(r2 - h2));
                ah[mt][3] = __float_as_uint(h3); al[mt][3] = __float_as_uint(f2tf32(r3 - h3));
            }
            LOAD_B_FRAGS(Bs_, kb)
#pragma unroll
            for (int mt = 0; mt < 2; mt++)
#pragma unroll
                for (int nt = 0; nt < 8; nt++) {
                    mma_tf32(acc[mt][nt], ah[mt][0], ah[mt][1], ah[mt][2], ah[mt][3],
                             bf[nt][0], bf[nt][1]);
                    mma_tf32(acc[mt][nt], al[mt][0], al[mt][1], al[mt][2], al[mt][3],
                             bf[nt][0], bf[nt][1]);
                }
        }
    }

    const int er = lane >> 2;
    const int ec = (lane & 3) << 1;
#pragma unroll
    for (int mt = 0; mt < 2; mt++) {
#pragma unroll
        for (int nt = 0; nt < 8; nt++) {
#pragma unroll
            for (int half = 0; half < 2; half++) {
                int m = row0 + wm + mt * 16 + er + half * 8;
                int n = col0 + wn + nt * 8 + ec;
                float2 v = make_float2(acc[mt][nt][half * 2] + bias[n],
                                       acc[mt][nt][half * 2 + 1] + bias[n + 1]);
                *(float2*)(Cout + (size_t)m * Cq + n) = v;
            }
        }
    }
}

// ---------------------------------------------------------------------------
// Fused attention, 64-row t-blocks, 128 threads (4 warps x 16 rows).
// One pass, no-max softmax. K/V double-buffered via cp.async (raw fp32 in
// smem; rna rounding at fragment read). Writes UNNORMALIZED E=exp(S) to wei
// (causal 64-granular tiles, sT = 0..tB). rescale_wei normalizes+zero-fills.
// ctx = (E·V)/l fp32 to g_ctx. 108KB smem -> 2 CTAs/SM.
// ---------------------------------------------------------------------------
#define AST 72
#define KVTILE (64 * AST)                              // floats per K or V buffer
#define ATTN_SMEM_FLOATS (64 * AST + 2 * KVTILE + 2 * KVTILE + 64 * AST)

__global__ __launch_bounds__(128, 2) void attn_fused(float* __restrict__ wei) {
    extern __shared__ float sm[];
    float* Qs  = sm;                      // [64][AST]
    float* KsB = Qs + 64 * AST;           // [2][KVTILE]
    float* VsB = KsB + 2 * KVTILE;        // [2][KVTILE]
    float* Ps  = VsB + 2 * KVTILE;        // [64][AST]

    const int tid  = threadIdx.x;
    const int wid  = tid >> 5;
    const int lane = tid & 31;
    const int tB   = blockIdx.x;          // 64-row t-block, 0..15
    const int bh   = blockIdx.y;
    const int wm   = wid * 16;            // warp row offset within 64-row block
    const int trow0 = tB * 64 + wm + (lane >> 2);
    const int trow1 = trow0 + 8;

    const float* qb = g_q + (size_t)bh * Tq * Dq + (size_t)tB * 64 * Dq;
    const float* kb = g_k + (size_t)bh * Tq * Dq;
    const float* vb = g_v + (size_t)bh * Tq * Dq;
    float* wb = wei + (size_t)bh * Tq * Tq + (size_t)tB * 64 * Tq;

    const uint32_t smb = smem_u32(sm);
    const uint32_t ksb = smb + (uint32_t)(64 * AST) * 4;
    const uint32_t vsb = ksb + (uint32_t)(2 * KVTILE) * 4;

#define ISSUE_KV(s_, buf_)                                                       \
    do {                                                                         \
        const float* kg = kb + (size_t)((s_) * 64) * Dq;                         \
        const float* vg = vb + (size_t)((s_) * 64) * Dq;                         \
        const uint32_t kd = ksb + (uint32_t)(buf_) * (KVTILE * 4);               \
        const uint32_t vd = vsb + (uint32_t)(buf_) * (KVTILE * 4);               \
        _Pragma("unroll")                                                        \
        for (int l2 = 0; l2 < 8; l2++) {                                         \
            int idx = tid + l2 * 128;                                            \
            int r2 = idx >> 4;                                                   \
            int c2 = (idx & 15) << 2;                                            \
            uint32_t off = (uint32_t)(r2 * AST + c2) * 4;                        \
            asm volatile("cp.async.cg.shared.global [%0], [%1], 16;"             \
                         :: "r"(kd + off), "l"(kg + r2 * Dq + c2));              \
            asm volatile("cp.async.cg.shared.global [%0], [%1], 16;"             \
                         :: "r"(vd + off), "l"(vg + r2 * Dq + c2));              \
        }                                                                        \
        asm volatile("cp.async.commit_group;");                                  \
    } while (0)

    // load Q tile (tf32-rounded, once)
#pragma unroll
    for (int l = 0; l < 8; l++) {
        int f = tid + l * 128;
        int r = f >> 4, c4 = (f & 15) << 2;
        float4 v = *(const float4*)(qb + (size_t)r * Dq + c4);
        Qs[r * AST + c4 + 0] = f2tf32(v.x);
        Qs[r * AST + c4 + 1] = f2tf32(v.y);
        Qs[r * AST + c4 + 2] = f2tf32(v.z);
        Qs[r * AST + c4 + 3] = f2tf32(v.w);
    }
    ISSUE_KV(0, 0);
    __syncthreads();

    // persistent Q fragments
    uint32_t af[8][4];
    {
        const int arow = wm + (lane >> 2);
#pragma unroll
        for (int ks = 0; ks < 8; ks++) {
            const int acol = ks * 8 + (lane & 3);
            af[ks][0] = __float_as_uint(Qs[(arow    ) * AST + acol    ]);
            af[ks][1] = __float_as_uint(Qs[(arow + 8) * AST + acol    ]);
            af[ks][2] = __float_as_uint(Qs[(arow    ) * AST + acol + 4]);
            af[ks][3] = __float_as_uint(Qs[(arow + 8) * AST + acol + 4]);
        }
    }

    const int nS = tB + 1;                 // tiles 0..tB (tB is the diagonal)
    float l0 = 0.f, l1 = 0.f;
    float ctx[8][4];
#pragma unroll
    for (int nt = 0; nt < 8; nt++)
        { ctx[nt][0]=0.f; ctx[nt][1]=0.f; ctx[nt][2]=0.f; ctx[nt][3]=0.f; }

    for (int sT = 0; sT < nS; sT++) {
        if (sT + 1 < nS) ISSUE_KV(sT + 1, (sT + 1) & 1);
        else asm volatile("cp.async.commit_group;");
        asm volatile("cp.async.wait_group 1;");
        __syncthreads();

        const float* Ks = KsB + (sT & 1) * KVTILE;
        const float* Vs = VsB + (sT & 1) * KVTILE;

        // S = Q·K^T
        float sacc[8][4];
#pragma unroll
        for (int nt = 0; nt < 8; nt++)
            { sacc[nt][0]=0.f; sacc[nt][1]=0.f; sacc[nt][2]=0.f; sacc[nt][3]=0.f; }
#pragma unroll
        for (int ks = 0; ks < 8; ks++) {
            uint32_t bf[8][2];
#pragma unroll
            for (int nt = 0; nt < 8; nt++) {
                int srow = nt * 8 + (lane >> 2);
                int scol = ks * 8 + (lane & 3);
                bf[nt][0] = __float_as_uint(f2tf32(Ks[srow * AST + scol]));
                bf[nt][1] = __float_as_uint(f2tf32(Ks[srow * AST + scol + 4]));
            }
#pragma unroll
            for (int nt = 0; nt < 8; nt++)
                mma_tf32(sacc[nt], af[ks][0], af[ks][1], af[ks][2], af[ks][3],
                         bf[nt][0], bf[nt][1]);
        }

        const bool mask = (sT == tB);      // diagonal tile
        {
            const int pr = wm + (lane >> 2);
            const int pc = (lane & 3) << 1;
#pragma unroll
            for (int nt = 0; nt < 8; nt++) {
                float s0v = sacc[nt][0] * 0.125f;
                float s1v = sacc[nt][1] * 0.125f;
                float s2v = sacc[nt][2] * 0.125f;
                float s3v = sacc[nt][3] * 0.125f;
                if (mask) {
                    int s0 = sT * 64 + nt * 8 + ((lane & 3) << 1);
                    if (s0     > trow0) s0v = -INFINITY;
                    if (s0 + 1 > trow0) s1v = -INFINITY;
                    if (s0     > trow1) s2v = -INFINITY;
                    if (s0 + 1 > trow1) s3v = -INFINITY;
                }
                float e0 = __expf(s0v), e1 = __expf(s1v);
                float e2 = __expf(s2v), e3 = __expf(s3v);
                l0 += e0 + e1;
                l1 += e2 + e3;
                Ps[(pr    ) * AST + nt * 8 + pc    ] = e0;
                Ps[(pr    ) * AST + nt * 8 + pc + 1] = e1;
                Ps[(pr + 8) * AST + nt * 8 + pc    ] = e2;
                Ps[(pr + 8) * AST + nt * 8 + pc + 1] = e3;
            }
        }
        __syncwarp();   // this warp's Ps rows complete

        // write unnormalized E for this warp's 16 rows
#pragma unroll
        for (int k = 0; k < 8; k++) {
            int idx = lane + k * 32;
            int rr = wm + (idx >> 4);
            int cc = (idx & 15) << 2;
            *(float4*)(wb + (size_t)rr * Tq + sT * 64 + cc) =
                *(const float4*)(Ps + rr * AST + cc);
        }

        // ctx += E·V (P rna-rounded at read; V rna-rounded at read)
#pragma unroll
        for (int ks = 0; ks < 8; ks++) {
            const int arow = wm + (lane >> 2);
            const int acol = ks * 8 + (lane & 3);
            uint32_t ap[4];
            ap[0] = __float_as_uint(f2tf32(Ps[(arow    ) * AST + acol    ]));
            ap[1] = __float_as_uint(f2tf32(Ps[(arow + 8) * AST + acol    ]));
            ap[2] = __float_as_uint(f2tf32(Ps[(arow    ) * AST + acol + 4]));
            ap[3] = __float_as_uint(f2tf32(Ps[(arow + 8) * AST + acol + 4]));
            uint32_t bv[8][2];
#pragma unroll
            for (int nt = 0; nt < 8; nt++) {
                int vrow = ks * 8 + (lane & 3);
                int vcol = nt * 8 + (lane >> 2);
                bv[nt][0] = __float_as_uint(f2tf32(Vs[(vrow    ) * AST + vcol]));
                bv[nt][1] = __float_as_uint(f2tf32(Vs[(vrow + 4) * AST + vcol]));
            }
#pragma unroll
            for (int nt = 0; nt < 8; nt++)
                mma_tf32(ctx[nt], ap[0], ap[1], ap[2], ap[3], bv[nt][0], bv[nt][1]);
        }
        __syncthreads();   // all warps done with this K/V buffer before reissue
    }

    l0 += __shfl_xor_sync(0xffffffffu, l0, 1);
    l0 += __shfl_xor_sync(0xffffffffu, l0, 2);
    l1 += __shfl_xor_sync(0xffffffffu, l1, 1);
    l1 += __shfl_xor_sync(0xffffffffu, l1, 2);
    const float inv0 = 1.0f / l0;
    const float inv1 = 1.0f / l1;

    if ((lane & 3) == 0) {
        g_invl[(size_t)bh * Tq + trow0] = inv0;
        g_invl[(size_t)bh * Tq + trow1] = inv1;
    }

    // write normalized ctx fp32 -> g_ctx [B,T,C]
    {
        const int b = bh >> 4, h = bh & 15;
        const int ec = (lane & 3) << 1;
#pragma unroll
        for (int nt = 0; nt < 8; nt++) {
            float2 v0 = {ctx[nt][0] * inv0, ctx[nt][1] * inv0};
            float2 v1 = {ctx[nt][2] * inv1, ctx[nt][3] * inv1};
            int c = h * 64 + nt * 8 + ec;
            *(float2*)(g_ctx + ((size_t)(b * Tq + trow0) << 10) + c) = v0;
            *(float2*)(g_ctx + ((size_t)(b * Tq + trow1) << 10) + c) = v1;
        }
    }
#undef ISSUE_KV
}

// ---------------------------------------------------------------------------
// Rescale + zero-fill wei. Row t: attn wrote cols [0, ((t>>6)+1)*64);
// scale that region by 1/l, zero the rest of the 1024 cols.
// ---------------------------------------------------------------------------
__global__ __launch_bounds__(256) void rescale_wei(float* __restrict__ wei) {
    const int bh = blockIdx.y;
    const int t  = blockIdx.x * 2 + (threadIdx.x >> 7);
    const int ln = threadIdx.x & 127;
    const float inv = g_invl[(size_t)bh * Tq + t];
    float4* row = (float4*)(wei + (size_t)bh * Tq * Tq + (size_t)t * Tq);
    const int n4c = ((t >> 6) + 1) * 16;   // written float4s (64-granular causal)
#pragma unroll 2
    for (int w = ln; w < n4c; w += 128) {
        float4 v = row[w];
        v.x *= inv; v.y *= inv; v.z *= inv; v.w *= inv;
        row[w] = v;
    }
    const float4 z = {0.f, 0.f, 0.f, 0.f};
#pragma unroll 2
    for (int w = n4c + ln; w < 256; w += 128) {
        row[w] = z;
    }
}

// ---------------------------------------------------------------------------
// Launch
// ---------------------------------------------------------------------------
extern "C" void kernel_launch(void* const* d_in, const int* in_sizes, int n_in,
                              void* d_out, int out_size) {
    const float* x     = (const float*)d_in[0];
    const float* Wq    = (const float*)d_in[1];
    const float* Wk    = (const float*)d_in[2];
    const float* Wv    = (const float*)d_in[3];
    const float* Wproj = (const float*)d_in[4];
    const float* bproj = (const float*)d_in[5];

    float* out = (float*)d_out;                       // [B,T,C]
    float* wei = out + (size_t)Bq * Tq * Cq;          // [B,H,T,T]

    float *pq, *pk, *pv, *pctx, *pwqkv, *pwp;
    cudaGetSymbolAddress((void**)&pq,    g_q);
    cudaGetSymbolAddress((void**)&pk,    g_k);
    cudaGetSymbolAddress((void**)&pv,    g_v);
    cudaGetSymbolAddress((void**)&pctx,  g_ctx);
    cudaGetSymbolAddress((void**)&pwqkv, g_wqkv);
    cudaGetSymbolAddress((void**)&pwp,   g_wp);

    const int attn_smem = ATTN_SMEM_FLOATS * 4;
    cudaFuncSetAttribute(attn_fused, cudaFuncAttributeMaxDynamicSharedMemorySize, attn_smem);
    cudaFuncSetAttribute(gemm_qkv,  cudaFuncAttributeMaxDynamicSharedMemorySize, GEMM_SMEM_BYTES);
    cudaFuncSetAttribute(gemm_proj, cudaFuncAttributeMaxDynamicSharedMemorySize, GEMM_SMEM_BYTES);

    // 1) weight repack / rounding (z=0..2: QKV; z=3: Wproj)
    dim3 gw((Cq * Cq) / 256, 4);
    conv_w_kernel<<<gw, 256>>>(Wq, Wk, Wv, Wproj, pwqkv, pwp);

    // 2) Q/K/V projections (reads raw x; rounds at fragment read)
    dim3 gqkv(Cq / 128, Mq / 128, 3);
    gemm_qkv<<<gqkv, 256, GEMM_SMEM_BYTES>>>(x, pwqkv, pq, pk, pv);

    // 3) fused one-pass attention, 64-row blocks (wei unnormalized, causal only)
    dim3 gattn(Tq / 64, BHq);
    attn_fused<<<gattn, 128, attn_smem>>>(wei);

    // 4) normalize + zero-fill wei rows
    dim3 grs(Tq / 2, BHq);
    rescale_wei<<<grs, 256>>>(wei);

    // 5) out = ctx @ Wproj^T + b (in-register 2-term split, K=1024)
    dim3 gout(Cq / 128, Mq / 128);
    gemm_proj<<<gout, 256, GEMM_SMEM_BYTES>>>(pctx, pwp, out, bproj);
}